// round 1
// baseline (speedup 1.0000x reference)
#include <cuda_runtime.h>
#include <cuda_bf16.h>
#include <math.h>

#define BB 2
#define TT 2048
#define DD 1024
#define NH 16
#define HD 64      // NOPE_D + ROPE_D
#define NOPE 48
#define ROPED 16
#define RR 128
#define VD 64
#define KVB_N (NH * (NOPE + VD))   // 1792
#define KVA_N (RR + ROPED)         // 144
#define MTOT (BB * TT)             // 4096

// ---------------- scratch (device globals; no allocs allowed) ----------------
__device__ float g_qraw[MTOT * NH * HD];     // x @ Wq^T            16 MB
__device__ float g_kva [MTOT * KVA_N];       // x @ Wkva^T          2.25 MB
__device__ float g_lat [MTOT * RR];          // rms(latent)         2 MB
__device__ float g_krope[MTOT * ROPED];      // roped k_rope        0.125 MB
__device__ float g_kvb [MTOT * KVB_N];       // lat @ Wkvb^T        28 MB
__device__ float g_qa  [BB * NH * TT * HD];  // q, attn layout      16 MB
__device__ float g_k   [BB * NH * TT * HD];  // k_full, attn layout 16 MB
__device__ float g_v   [BB * NH * TT * VD];  // v, attn layout      16 MB
__device__ float g_ao  [MTOT * NH * VD];     // attn out [bt, h*64+d] 16 MB

// ---------------- GEMM: C[M,N] = A[M,K] @ B[N,K]^T ----------------
// 64x64 tile, BK=16, 256 threads, 4x4 per thread.
__global__ __launch_bounds__(256) void gemm_tn(
    const float* __restrict__ A, const float* __restrict__ Bm,
    float* __restrict__ C, int M, int N, int K)
{
    __shared__ float As[16][68];  // transposed, pad 4 keeps float4 alignment
    __shared__ float Bs[16][68];
    const int tx = threadIdx.x & 15;
    const int ty = threadIdx.x >> 4;
    const int m0 = blockIdx.y * 64;
    const int n0 = blockIdx.x * 64;

    float acc[4][4] = {};

    for (int k0 = 0; k0 < K; k0 += 16) {
        #pragma unroll
        for (int i = threadIdx.x; i < 64 * 16; i += 256) {
            int r = i >> 4, c = i & 15;
            float av = (m0 + r < M) ? A[(size_t)(m0 + r) * K + k0 + c] : 0.f;
            float bv = (n0 + r < N) ? Bm[(size_t)(n0 + r) * K + k0 + c] : 0.f;
            As[c][r] = av;
            Bs[c][r] = bv;
        }
        __syncthreads();
        #pragma unroll
        for (int k = 0; k < 16; k++) {
            float4 a4 = *(const float4*)&As[k][ty * 4];
            float4 b4 = *(const float4*)&Bs[k][tx * 4];
            float a[4] = {a4.x, a4.y, a4.z, a4.w};
            float b[4] = {b4.x, b4.y, b4.z, b4.w};
            #pragma unroll
            for (int i = 0; i < 4; i++)
                #pragma unroll
                for (int j = 0; j < 4; j++)
                    acc[i][j] += a[i] * b[j];
        }
        __syncthreads();
    }
    #pragma unroll
    for (int i = 0; i < 4; i++) {
        int m = m0 + ty * 4 + i;
        if (m >= M) continue;
        #pragma unroll
        for (int j = 0; j < 4; j++) {
            int n = n0 + tx * 4 + j;
            if (n < N) C[(size_t)m * N + n] = acc[i][j];
        }
    }
}

// ---------------- q post: per-head RMS norm + RoPE, relayout to [b,h,t,d] ----
__global__ __launch_bounds__(64) void q_post_kernel(
    const float* __restrict__ cosp, const float* __restrict__ sinp,
    const float* __restrict__ qw)
{
    int bid = blockIdx.x;           // (b*T + t)*NH + h
    int h   = bid & (NH - 1);
    int bt  = bid >> 4;
    int t   = bt & (TT - 1);
    int b   = bt >> 11;
    int d   = threadIdx.x;

    float v = g_qraw[(size_t)bt * (NH * HD) + h * HD + d];
    float ss = v * v;
    #pragma unroll
    for (int o = 16; o; o >>= 1) ss += __shfl_xor_sync(~0u, ss, o);
    __shared__ float red[2];
    if ((threadIdx.x & 31) == 0) red[threadIdx.x >> 5] = ss;
    __syncthreads();
    float tot = red[0] + red[1];
    float norm = rsqrtf(tot * (1.0f / HD) + 1e-6f);
    float qn = v * norm * qw[d];

    float pv = __shfl_xor_sync(~0u, qn, 8);
    if (d >= NOPE) {
        int i = d & 7;
        float c = cosp[t * 8 + i], s = sinp[t * 8 + i];
        qn = (d < NOPE + 8) ? (qn * c - pv * s) : (qn * c + pv * s);
    }
    g_qa[(((size_t)(b * NH + h)) * TT + t) * HD + d] = qn;
}

// ---------------- kv_a post: latent RMS norm + k_rope RoPE ----------------
__global__ __launch_bounds__(128) void kva_post_kernel(
    const float* __restrict__ cosp, const float* __restrict__ sinp,
    const float* __restrict__ kvaw)
{
    int bt = blockIdx.x;
    int t  = bt & (TT - 1);
    int tid = threadIdx.x;

    float v = g_kva[(size_t)bt * KVA_N + tid];
    float ss = v * v;
    #pragma unroll
    for (int o = 16; o; o >>= 1) ss += __shfl_xor_sync(~0u, ss, o);
    __shared__ float red[4];
    if ((tid & 31) == 0) red[tid >> 5] = ss;
    __syncthreads();
    float tot = red[0] + red[1] + red[2] + red[3];
    float norm = rsqrtf(tot * (1.0f / RR) + 1e-6f);
    g_lat[(size_t)bt * RR + tid] = v * norm * kvaw[tid];

    if (tid < 32) {  // warp 0 handles the 16-dim rope
        float rv = (tid < ROPED) ? g_kva[(size_t)bt * KVA_N + RR + tid] : 0.f;
        float pv = __shfl_xor_sync(~0u, rv, 8);
        if (tid < ROPED) {
            int i = tid & 7;
            float c = cosp[t * 8 + i], s = sinp[t * 8 + i];
            float outv = (tid < 8) ? (rv * c - pv * s) : (rv * c + pv * s);
            g_krope[(size_t)bt * ROPED + tid] = outv;
        }
    }
}

// ---------------- assemble k_full / v into [b,h,t,d] ----------------
__global__ __launch_bounds__(256) void assemble_kernel()
{
    const int NTOT = BB * NH * TT * HD;
    for (int idx = blockIdx.x * blockDim.x + threadIdx.x; idx < NTOT;
         idx += gridDim.x * blockDim.x) {
        int d = idx & 63;
        int t = (idx >> 6) & (TT - 1);
        int h = (idx >> 17) & (NH - 1);
        int b = idx >> 21;
        size_t bt = (size_t)b * TT + t;
        float kv;
        if (d < NOPE) kv = g_kvb[bt * KVB_N + h * (NOPE + VD) + d];
        else          kv = g_krope[bt * ROPED + (d - NOPE)];
        g_k[idx] = kv;
        g_v[idx] = g_kvb[bt * KVB_N + h * (NOPE + VD) + NOPE + d];
    }
}

// ---------------- flash attention: 1 thread = 1 query row ----------------
// grid (T/128, B*NH), 128 threads. smem: K[64][64], V[64][64], S[128][65].
__global__ __launch_bounds__(128) void flash_kernel()
{
    extern __shared__ float sm[];
    float* Ks = sm;                 // 64*64
    float* Vs = sm + 64 * 64;       // 64*64
    float* Sc = sm + 2 * 64 * 64;   // 128*65

    const int bh = blockIdx.y;
    const int b = bh >> 4, h = bh & (NH - 1);
    const int tid = threadIdx.x;
    const int tq = blockIdx.x * 128 + tid;

    const float* qp = g_qa + ((size_t)bh * TT + tq) * HD;
    float q[HD], o[HD];
    #pragma unroll
    for (int d4 = 0; d4 < HD / 4; d4++) {
        float4 v4 = ((const float4*)qp)[d4];
        q[d4 * 4 + 0] = v4.x; q[d4 * 4 + 1] = v4.y;
        q[d4 * 4 + 2] = v4.z; q[d4 * 4 + 3] = v4.w;
    }
    #pragma unroll
    for (int d = 0; d < HD; d++) o[d] = 0.f;

    float mrow = -1e30f, ssum = 0.f;
    const float scale = 0.125f;  // 64^-0.5
    const int ntiles = (blockIdx.x + 1) * 2;
    const float* Kbase = g_k + (size_t)bh * TT * HD;
    const float* Vbase = g_v + (size_t)bh * TT * VD;

    for (int it = 0; it < ntiles; it++) {
        const int j0 = it * 64;
        __syncthreads();
        #pragma unroll
        for (int i = tid; i < 64 * 16; i += 128) {
            ((float4*)Ks)[i] = ((const float4*)(Kbase + (size_t)j0 * HD))[i];
            ((float4*)Vs)[i] = ((const float4*)(Vbase + (size_t)j0 * VD))[i];
        }
        __syncthreads();

        float tmax = -1e30f;
        for (int j = 0; j < 64; j++) {
            const float4* kr = (const float4*)(Ks + j * HD);
            float dot = 0.f;
            #pragma unroll
            for (int d4 = 0; d4 < 16; d4++) {
                float4 k4 = kr[d4];
                dot += q[d4 * 4 + 0] * k4.x + q[d4 * 4 + 1] * k4.y
                     + q[d4 * 4 + 2] * k4.z + q[d4 * 4 + 3] * k4.w;
            }
            float x = (j0 + j <= tq) ? dot * scale : -1e30f;
            Sc[tid * 65 + j] = x;
            tmax = fmaxf(tmax, x);
        }
        float mnew = fmaxf(mrow, tmax);
        float corr = __expf(mrow - mnew);
        ssum *= corr;
        #pragma unroll
        for (int d = 0; d < HD; d++) o[d] *= corr;

        for (int j = 0; j < 64; j++) {
            float p = __expf(Sc[tid * 65 + j] - mnew);
            ssum += p;
            const float4* vr = (const float4*)(Vs + j * VD);
            #pragma unroll
            for (int d4 = 0; d4 < 16; d4++) {
                float4 v4 = vr[d4];
                o[d4 * 4 + 0] += p * v4.x;
                o[d4 * 4 + 1] += p * v4.y;
                o[d4 * 4 + 2] += p * v4.z;
                o[d4 * 4 + 3] += p * v4.w;
            }
        }
        mrow = mnew;
    }

    float inv = 1.f / ssum;
    float* op = g_ao + ((size_t)(b * TT + tq)) * (NH * VD) + h * VD;
    #pragma unroll
    for (int d4 = 0; d4 < 16; d4++) {
        float4 v4 = make_float4(o[d4 * 4 + 0] * inv, o[d4 * 4 + 1] * inv,
                                o[d4 * 4 + 2] * inv, o[d4 * 4 + 3] * inv);
        ((float4*)op)[d4] = v4;
    }
}

// ---------------- launch ----------------
static float* sym_addr(const void* symbol) {
    void* p = nullptr;
    cudaGetSymbolAddress(&p, symbol);
    return (float*)p;
}

extern "C" void kernel_launch(void* const* d_in, const int* in_sizes, int n_in,
                              void* d_out, int out_size)
{
    const float* x    = (const float*)d_in[0];
    const float* cosp = (const float*)d_in[1];
    const float* sinp = (const float*)d_in[2];
    const float* Wq   = (const float*)d_in[3];
    const float* qw   = (const float*)d_in[4];
    const float* Wkva = (const float*)d_in[5];
    const float* kvaw = (const float*)d_in[6];
    const float* Wkvb = (const float*)d_in[7];
    const float* Wo   = (const float*)d_in[8];
    float* out = (float*)d_out;

    float* qraw = sym_addr(g_qraw);
    float* kva  = sym_addr(g_kva);
    float* lat  = sym_addr(g_lat);
    float* kvb  = sym_addr(g_kvb);
    float* ao   = sym_addr(g_ao);

    // 1) q projection + kv_a projection
    {
        dim3 g(DD / 64, MTOT / 64);
        gemm_tn<<<g, 256>>>(x, Wq, qraw, MTOT, NH * HD, DD);
    }
    {
        dim3 g((KVA_N + 63) / 64, MTOT / 64);
        gemm_tn<<<g, 256>>>(x, Wkva, kva, MTOT, KVA_N, DD);
    }

    // 2) norms + rope
    q_post_kernel<<<MTOT * NH, 64>>>(cosp, sinp, qw);
    kva_post_kernel<<<MTOT, 128>>>(cosp, sinp, kvaw);

    // 3) kv_b projection + assemble
    {
        dim3 g(KVB_N / 64, MTOT / 64);
        gemm_tn<<<g, 256>>>(lat, Wkvb, kvb, MTOT, KVB_N, RR);
    }
    assemble_kernel<<<4096, 256>>>();

    // 4) flash attention
    {
        const int smem = (2 * 64 * 64 + 128 * 65) * (int)sizeof(float);  // 66048
        cudaFuncSetAttribute(flash_kernel,
                             cudaFuncAttributeMaxDynamicSharedMemorySize, smem);
        dim3 g(TT / 128, BB * NH);
        flash_kernel<<<g, 128, smem>>>();
    }

    // 5) output projection
    {
        dim3 g(DD / 64, MTOT / 64);
        gemm_tn<<<g, 256>>>(ao, Wo, out, MTOT, DD, NH * VD);
    }
}

// round 3
// speedup vs baseline: 1.2544x; 1.2544x over previous
#include <cuda_runtime.h>
#include <cuda_bf16.h>
#include <math.h>
#include <cstdint>

#define BB 2
#define TT 2048
#define DD 1024
#define NH 16
#define HD 64      // NOPE_D + ROPE_D
#define NOPE 48
#define ROPED 16
#define RR 128
#define VD 64
#define KVB_N (NH * (NOPE + VD))   // 1792
#define KVA_N (RR + ROPED)         // 144
#define KVA_PAD 256
#define MTOT (BB * TT)             // 4096

// ---------------- scratch (device globals; no allocs allowed) ----------------
__device__ float g_qraw[MTOT * NH * HD];
__device__ float g_kva [MTOT * KVA_N];
__device__ float g_lat [MTOT * RR];
__device__ float g_krope[MTOT * ROPED];
__device__ float g_kvb [MTOT * KVB_N];
__device__ float g_qa  [BB * NH * TT * HD];
__device__ float g_k   [BB * NH * TT * HD];
__device__ float g_v   [BB * NH * TT * VD];
__device__ float g_ao  [MTOT * NH * VD];

// bf16 triple-split buffers: A' = [hi|hi|lo] along K, B' = [hi|lo|hi]
__device__ __align__(256) __nv_bfloat16 g_xq [MTOT * 3 * DD];     // x (A side)
__device__ __align__(256) __nv_bfloat16 g_Wq3[DD * 3 * DD];
__device__ __align__(256) __nv_bfloat16 g_Wa3[KVA_PAD * 3 * DD];
__device__ __align__(256) __nv_bfloat16 g_Wb3[KVB_N * 3 * RR];
__device__ __align__(256) __nv_bfloat16 g_Wo3[DD * 3 * DD];
__device__ __align__(256) __nv_bfloat16 g_l3 [MTOT * 3 * RR];
__device__ __align__(256) __nv_bfloat16 g_a3 [MTOT * 3 * DD];

// ======================= fp32 -> bf16 triple-split convert =======================
// out[row, 0:K]=hi ; out[row, K:2K]= (mode==0 ? hi : lo) ; out[row, 2K:3K]= (mode==0 ? lo : hi)
__global__ __launch_bounds__(256) void cvt_triple(
    const float* __restrict__ s, __nv_bfloat16* __restrict__ o,
    int K, int npad_elems, int nreal_elems, int mode)
{
    int stride = gridDim.x * blockDim.x * 4;
    for (int e = (blockIdx.x * blockDim.x + threadIdx.x) * 4; e < npad_elems; e += stride) {
        float4 v = (e < nreal_elems) ? *(const float4*)(s + e)
                                     : make_float4(0.f, 0.f, 0.f, 0.f);
        __nv_bfloat16 h[4], l[4];
        h[0] = __float2bfloat16(v.x); l[0] = __float2bfloat16(v.x - __bfloat162float(h[0]));
        h[1] = __float2bfloat16(v.y); l[1] = __float2bfloat16(v.y - __bfloat162float(h[1]));
        h[2] = __float2bfloat16(v.z); l[2] = __float2bfloat16(v.z - __bfloat162float(h[2]));
        h[3] = __float2bfloat16(v.w); l[3] = __float2bfloat16(v.w - __bfloat162float(h[3]));
        int row = e / K, col = e % K;
        __nv_bfloat16* base = o + (size_t)row * (3 * K) + col;
        __nv_bfloat162 hp0(h[0], h[1]), hp1(h[2], h[3]);
        __nv_bfloat162 lp0(l[0], l[1]), lp1(l[2], l[3]);
        ((__nv_bfloat162*)(base))[0] = hp0;           ((__nv_bfloat162*)(base))[1] = hp1;
        if (mode == 0) {
            ((__nv_bfloat162*)(base + K))[0] = hp0;   ((__nv_bfloat162*)(base + K))[1] = hp1;
            ((__nv_bfloat162*)(base + 2*K))[0] = lp0; ((__nv_bfloat162*)(base + 2*K))[1] = lp1;
        } else {
            ((__nv_bfloat162*)(base + K))[0] = lp0;   ((__nv_bfloat162*)(base + K))[1] = lp1;
            ((__nv_bfloat162*)(base + 2*K))[0] = hp0; ((__nv_bfloat162*)(base + 2*K))[1] = hp1;
        }
    }
}

// ======================= HMMA GEMM =======================
// C[M, Nreal] (ld=ldc) = A'[M,Kp] @ B'[Npad,Kp]^T, bf16 in, fp32 acc.
// CTA tile 128x128, warp tile 64x32, BK=32, cp.async double buffer.
#define GPAD 40                       // padded row stride (elements)
#define GTILE_B (128 * GPAD * 2)      // 10240 bytes per matrix tile
#define GBUF_B  (2 * GTILE_B)         // 20480 per stage

__global__ __launch_bounds__(256) void hmma_gemm(
    const __nv_bfloat16* __restrict__ Ap, const __nv_bfloat16* __restrict__ Bp,
    float* __restrict__ C, int Kp, int Nreal, int ldc)
{
    __shared__ __align__(16) char smem[2 * GBUF_B];   // 40 KB

    const int tid = threadIdx.x, wid = tid >> 5, lane = tid & 31;
    const int warp_m = wid >> 2, warp_n = wid & 3;    // 2 x 4 warps
    const int m0 = blockIdx.y * 128, n0 = blockIdx.x * 128;

    uint32_t smem_base;
    asm("{ .reg .u64 t; cvta.to.shared.u64 t, %1; cvt.u32.u64 %0, t; }"
        : "=r"(smem_base) : "l"((void*)smem));

    const char* Abase = (const char*)(Ap + (size_t)m0 * Kp);
    const char* Bbase = (const char*)(Bp + (size_t)n0 * Kp);
    const size_t ldbytes = (size_t)Kp * 2;
    const int nch = Kp >> 5;

    float acc[4][4][4];
    #pragma unroll
    for (int i = 0; i < 4; i++)
        #pragma unroll
        for (int j = 0; j < 4; j++)
            #pragma unroll
            for (int e = 0; e < 4; e++) acc[i][j][e] = 0.f;

    // per-thread load plan: 4 x 16B segments (A:512 segs, B:512 segs)
    auto load_chunk = [&](int ch, int buf) {
        const int k0b = (ch << 5) * 2;   // byte offset along K
        #pragma unroll
        for (int it = 0; it < 4; it++) {
            int i = tid + it * 256;                  // 0..1023
            int mat = i >> 9, rem = i & 511;
            int row = rem >> 2, seg = rem & 3;
            const char* src = (mat ? Bbase : Abase) + (size_t)row * ldbytes + k0b + seg * 16;
            uint32_t dst = smem_base + buf * GBUF_B + mat * GTILE_B
                         + (row * GPAD + seg * 8) * 2;
            asm volatile("cp.async.cg.shared.global [%0], [%1], 16;" :: "r"(dst), "l"(src));
        }
        asm volatile("cp.async.commit_group;");
    };

    auto compute_chunk = [&](int buf) {
        const uint32_t smA = smem_base + buf * GBUF_B;
        const uint32_t smB = smA + GTILE_B;
        const int lm = lane & 15, lh = lane >> 4;
        const int g = lane >> 3, r = lane & 7;
        #pragma unroll
        for (int k16 = 0; k16 < 2; k16++) {
            uint32_t a[4][4];
            #pragma unroll
            for (int fm = 0; fm < 4; fm++) {
                uint32_t addr = smA + ((warp_m * 64 + fm * 16 + lm) * GPAD
                                       + k16 * 16 + lh * 8) * 2;
                asm volatile("ldmatrix.sync.aligned.m8n8.x4.shared.b16 {%0,%1,%2,%3}, [%4];"
                    : "=r"(a[fm][0]), "=r"(a[fm][1]), "=r"(a[fm][2]), "=r"(a[fm][3])
                    : "r"(addr));
            }
            uint32_t b[4][2];
            #pragma unroll
            for (int fp = 0; fp < 2; fp++) {   // each x4 covers 2 n-frags
                int row = warp_n * 32 + fp * 16 + ((g >> 1) << 3) + r;
                int col = (g & 1) * 8 + k16 * 16;
                uint32_t addr = smB + (row * GPAD + col) * 2;
                asm volatile("ldmatrix.sync.aligned.m8n8.x4.shared.b16 {%0,%1,%2,%3}, [%4];"
                    : "=r"(b[fp*2][0]), "=r"(b[fp*2][1]),
                      "=r"(b[fp*2+1][0]), "=r"(b[fp*2+1][1])
                    : "r"(addr));
            }
            #pragma unroll
            for (int fm = 0; fm < 4; fm++)
                #pragma unroll
                for (int fn = 0; fn < 4; fn++) {
                    asm volatile(
                        "mma.sync.aligned.m16n8k16.row.col.f32.bf16.bf16.f32 "
                        "{%0,%1,%2,%3}, {%4,%5,%6,%7}, {%8,%9}, {%0,%1,%2,%3};"
                        : "+f"(acc[fm][fn][0]), "+f"(acc[fm][fn][1]),
                          "+f"(acc[fm][fn][2]), "+f"(acc[fm][fn][3])
                        : "r"(a[fm][0]), "r"(a[fm][1]), "r"(a[fm][2]), "r"(a[fm][3]),
                          "r"(b[fn][0]), "r"(b[fn][1]));
                }
        }
    };

    load_chunk(0, 0);
    asm volatile("cp.async.wait_group 0;");
    __syncthreads();

    for (int ch = 0; ch < nch; ch++) {
        const int buf = ch & 1;
        if (ch + 1 < nch) load_chunk(ch + 1, buf ^ 1);
        compute_chunk(buf);
        asm volatile("cp.async.wait_group 0;");
        __syncthreads();
    }

    // epilogue
    const int r4 = lane >> 2, c2 = (lane & 3) * 2;
    #pragma unroll
    for (int fm = 0; fm < 4; fm++) {
        #pragma unroll
        for (int fn = 0; fn < 4; fn++) {
            int m = m0 + warp_m * 64 + fm * 16 + r4;
            int n = n0 + warp_n * 32 + fn * 8 + c2;
            if (n < Nreal) {
                *(float2*)&C[(size_t)m * ldc + n] =
                    make_float2(acc[fm][fn][0], acc[fm][fn][1]);
                *(float2*)&C[(size_t)(m + 8) * ldc + n] =
                    make_float2(acc[fm][fn][2], acc[fm][fn][3]);
            }
        }
    }
}

// ---------------- q post: per-head RMS norm + RoPE, relayout to [b,h,t,d] ----
__global__ __launch_bounds__(64) void q_post_kernel(
    const float* __restrict__ cosp, const float* __restrict__ sinp,
    const float* __restrict__ qw)
{
    int bid = blockIdx.x;
    int h   = bid & (NH - 1);
    int bt  = bid >> 4;
    int t   = bt & (TT - 1);
    int b   = bt >> 11;
    int d   = threadIdx.x;

    float v = g_qraw[(size_t)bt * (NH * HD) + h * HD + d];
    float ss = v * v;
    #pragma unroll
    for (int o = 16; o; o >>= 1) ss += __shfl_xor_sync(~0u, ss, o);
    __shared__ float red[2];
    if ((threadIdx.x & 31) == 0) red[threadIdx.x >> 5] = ss;
    __syncthreads();
    float tot = red[0] + red[1];
    float norm = rsqrtf(tot * (1.0f / HD) + 1e-6f);
    float qn = v * norm * qw[d];

    float pv = __shfl_xor_sync(~0u, qn, 8);
    if (d >= NOPE) {
        int i = d & 7;
        float c = cosp[t * 8 + i], s = sinp[t * 8 + i];
        qn = (d < NOPE + 8) ? (qn * c - pv * s) : (qn * c + pv * s);
    }
    g_qa[(((size_t)(b * NH + h)) * TT + t) * HD + d] = qn;
}

// ---------------- kv_a post ----------------
__global__ __launch_bounds__(128) void kva_post_kernel(
    const float* __restrict__ cosp, const float* __restrict__ sinp,
    const float* __restrict__ kvaw)
{
    int bt = blockIdx.x;
    int t  = bt & (TT - 1);
    int tid = threadIdx.x;

    float v = g_kva[(size_t)bt * KVA_N + tid];
    float ss = v * v;
    #pragma unroll
    for (int o = 16; o; o >>= 1) ss += __shfl_xor_sync(~0u, ss, o);
    __shared__ float red[4];
    if ((tid & 31) == 0) red[tid >> 5] = ss;
    __syncthreads();
    float tot = red[0] + red[1] + red[2] + red[3];
    float norm = rsqrtf(tot * (1.0f / RR) + 1e-6f);
    g_lat[(size_t)bt * RR + tid] = v * norm * kvaw[tid];

    if (tid < 32) {
        float rv = (tid < ROPED) ? g_kva[(size_t)bt * KVA_N + RR + tid] : 0.f;
        float pv = __shfl_xor_sync(~0u, rv, 8);
        if (tid < ROPED) {
            int i = tid & 7;
            float c = cosp[t * 8 + i], s = sinp[t * 8 + i];
            float outv = (tid < 8) ? (rv * c - pv * s) : (rv * c + pv * s);
            g_krope[(size_t)bt * ROPED + tid] = outv;
        }
    }
}

// ---------------- assemble k_full / v into [b,h,t,d] ----------------
__global__ __launch_bounds__(256) void assemble_kernel()
{
    const int NTOT = BB * NH * TT * HD;
    for (int idx = blockIdx.x * blockDim.x + threadIdx.x; idx < NTOT;
         idx += gridDim.x * blockDim.x) {
        int d = idx & 63;
        int t = (idx >> 6) & (TT - 1);
        int h = (idx >> 17) & (NH - 1);
        int b = idx >> 21;
        size_t bt = (size_t)b * TT + t;
        float kv;
        if (d < NOPE) kv = g_kvb[bt * KVB_N + h * (NOPE + VD) + d];
        else          kv = g_krope[bt * ROPED + (d - NOPE)];
        g_k[idx] = kv;
        g_v[idx] = g_kvb[bt * KVB_N + h * (NOPE + VD) + NOPE + d];
    }
}

// ---------------- flash attention: 1 thread = 1 query row ----------------
__global__ __launch_bounds__(128) void flash_kernel()
{
    extern __shared__ float sm[];
    float* Ks = sm;
    float* Vs = sm + 64 * 64;
    float* Sc = sm + 2 * 64 * 64;

    const int bh = blockIdx.y;
    const int b = bh >> 4, h = bh & (NH - 1);
    const int tid = threadIdx.x;
    const int tq = blockIdx.x * 128 + tid;

    const float* qp = g_qa + ((size_t)bh * TT + tq) * HD;
    float q[HD], o[HD];
    #pragma unroll
    for (int d4 = 0; d4 < HD / 4; d4++) {
        float4 v4 = ((const float4*)qp)[d4];
        q[d4 * 4 + 0] = v4.x; q[d4 * 4 + 1] = v4.y;
        q[d4 * 4 + 2] = v4.z; q[d4 * 4 + 3] = v4.w;
    }
    #pragma unroll
    for (int d = 0; d < HD; d++) o[d] = 0.f;

    float mrow = -1e30f, ssum = 0.f;
    const float scale = 0.125f;
    const int ntiles = (blockIdx.x + 1) * 2;
    const float* Kbase = g_k + (size_t)bh * TT * HD;
    const float* Vbase = g_v + (size_t)bh * TT * VD;

    for (int it = 0; it < ntiles; it++) {
        const int j0 = it * 64;
        __syncthreads();
        #pragma unroll
        for (int i = tid; i < 64 * 16; i += 128) {
            ((float4*)Ks)[i] = ((const float4*)(Kbase + (size_t)j0 * HD))[i];
            ((float4*)Vs)[i] = ((const float4*)(Vbase + (size_t)j0 * VD))[i];
        }
        __syncthreads();

        float tmax = -1e30f;
        for (int j = 0; j < 64; j++) {
            const float4* kr = (const float4*)(Ks + j * HD);
            float dot = 0.f;
            #pragma unroll
            for (int d4 = 0; d4 < 16; d4++) {
                float4 k4 = kr[d4];
                dot += q[d4 * 4 + 0] * k4.x + q[d4 * 4 + 1] * k4.y
                     + q[d4 * 4 + 2] * k4.z + q[d4 * 4 + 3] * k4.w;
            }
            float x = (j0 + j <= tq) ? dot * scale : -1e30f;
            Sc[tid * 65 + j] = x;
            tmax = fmaxf(tmax, x);
        }
        float mnew = fmaxf(mrow, tmax);
        float corr = __expf(mrow - mnew);
        ssum *= corr;
        #pragma unroll
        for (int d = 0; d < HD; d++) o[d] *= corr;

        for (int j = 0; j < 64; j++) {
            float p = __expf(Sc[tid * 65 + j] - mnew);
            ssum += p;
            const float4* vr = (const float4*)(Vs + j * VD);
            #pragma unroll
            for (int d4 = 0; d4 < 16; d4++) {
                float4 v4 = vr[d4];
                o[d4 * 4 + 0] += p * v4.x;
                o[d4 * 4 + 1] += p * v4.y;
                o[d4 * 4 + 2] += p * v4.z;
                o[d4 * 4 + 3] += p * v4.w;
            }
        }
        mrow = mnew;
    }

    float inv = 1.f / ssum;
    float* op = g_ao + ((size_t)(b * TT + tq)) * (NH * VD) + h * VD;
    #pragma unroll
    for (int d4 = 0; d4 < 16; d4++) {
        float4 v4 = make_float4(o[d4 * 4 + 0] * inv, o[d4 * 4 + 1] * inv,
                                o[d4 * 4 + 2] * inv, o[d4 * 4 + 3] * inv);
        ((float4*)op)[d4] = v4;
    }
}

// ---------------- launch ----------------
static void* sym_addr(const void* symbol) {
    void* p = nullptr;
    cudaGetSymbolAddress(&p, symbol);
    return p;
}

static void launch_cvt(const float* src, void* o, int K, int npad_rows, int nreal_rows, int mode) {
    int npad_elems = npad_rows * K;
    int blocks = (npad_elems / 4 + 255) / 256;
    if (blocks > 16384) blocks = 16384;
    cvt_triple<<<blocks, 256>>>(src, (__nv_bfloat16*)o, K, npad_elems, nreal_rows * K, mode);
}

extern "C" void kernel_launch(void* const* d_in, const int* in_sizes, int n_in,
                              void* d_out, int out_size)
{
    const float* x    = (const float*)d_in[0];
    const float* cosp = (const float*)d_in[1];
    const float* sinp = (const float*)d_in[2];
    const float* Wq   = (const float*)d_in[3];
    const float* qw   = (const float*)d_in[4];
    const float* Wkva = (const float*)d_in[5];
    const float* kvaw = (const float*)d_in[6];
    const float* Wkvb = (const float*)d_in[7];
    const float* Wo   = (const float*)d_in[8];
    float* out = (float*)d_out;

    float* qraw = (float*)sym_addr(g_qraw);
    float* kva  = (float*)sym_addr(g_kva);
    float* lat  = (float*)sym_addr(g_lat);
    float* kvb  = (float*)sym_addr(g_kvb);
    float* ao   = (float*)sym_addr(g_ao);

    __nv_bfloat16* xq  = (__nv_bfloat16*)sym_addr(g_xq);
    __nv_bfloat16* wq3 = (__nv_bfloat16*)sym_addr(g_Wq3);
    __nv_bfloat16* wa3 = (__nv_bfloat16*)sym_addr(g_Wa3);
    __nv_bfloat16* wb3 = (__nv_bfloat16*)sym_addr(g_Wb3);
    __nv_bfloat16* wo3 = (__nv_bfloat16*)sym_addr(g_Wo3);
    __nv_bfloat16* l3  = (__nv_bfloat16*)sym_addr(g_l3);
    __nv_bfloat16* a3  = (__nv_bfloat16*)sym_addr(g_a3);

    // 0) triple-split conversions (A-side mode 0: hi|hi|lo ; B-side mode 1: hi|lo|hi)
    launch_cvt(x,    xq,  DD, MTOT,    MTOT,  0);
    launch_cvt(Wq,   wq3, DD, DD,      DD,    1);
    launch_cvt(Wkva, wa3, DD, KVA_PAD, KVA_N, 1);
    launch_cvt(Wkvb, wb3, RR, KVB_N,   KVB_N, 1);
    launch_cvt(Wo,   wo3, DD, DD,      DD,    1);

    // 1) q projection (K'=3072) + kv_a projection (Npad=256)
    {
        dim3 g(DD / 128, MTOT / 128);
        hmma_gemm<<<g, 256>>>(xq, wq3, qraw, 3 * DD, NH * HD, NH * HD);
    }
    {
        dim3 g(KVA_PAD / 128, MTOT / 128);
        hmma_gemm<<<g, 256>>>(xq, wa3, kva, 3 * DD, KVA_N, KVA_N);
    }

    // 2) norms + rope
    q_post_kernel<<<MTOT * NH, 64>>>(cosp, sinp, qw);
    kva_post_kernel<<<MTOT, 128>>>(cosp, sinp, kvaw);

    // 3) kv_b projection (K'=384) + assemble
    launch_cvt(lat, l3, RR, MTOT, MTOT, 0);
    {
        dim3 g(KVB_N / 128, MTOT / 128);
        hmma_gemm<<<g, 256>>>(l3, wb3, kvb, 3 * RR, KVB_N, KVB_N);
    }
    assemble_kernel<<<4096, 256>>>();

    // 4) flash attention
    {
        const int smem = (2 * 64 * 64 + 128 * 65) * (int)sizeof(float);
        cudaFuncSetAttribute(flash_kernel,
                             cudaFuncAttributeMaxDynamicSharedMemorySize, smem);
        dim3 g(TT / 128, BB * NH);
        flash_kernel<<<g, 128, smem>>>();
    }

    // 5) output projection (K'=3072)
    launch_cvt(ao, a3, DD, MTOT, MTOT, 0);
    {
        dim3 g(DD / 128, MTOT / 128);
        hmma_gemm<<<g, 256>>>(a3, wo3, out, 3 * DD, DD, DD);
    }
}

// round 4
// speedup vs baseline: 2.5175x; 2.0069x over previous
#include <cuda_runtime.h>
#include <cuda_bf16.h>
#include <math.h>
#include <cstdint>

#define BB 2
#define TT 2048
#define DD 1024
#define NH 16
#define HD 64      // NOPE_D + ROPE_D
#define NOPE 48
#define ROPED 16
#define RR 128
#define VD 64
#define KVB_N (NH * (NOPE + VD))   // 1792
#define KVA_N (RR + ROPED)         // 144
#define KVA_PAD 256
#define MTOT (BB * TT)             // 4096

// ---------------- scratch (device globals; no allocs allowed) ----------------
__device__ float g_qraw[MTOT * NH * HD];
__device__ float g_kva [MTOT * KVA_N];
__device__ float g_lat [MTOT * RR];
__device__ float g_krope[MTOT * ROPED];
__device__ float g_kvb [MTOT * KVB_N];
__device__ float g_ao  [MTOT * NH * VD];

// attention operands, bf16 hi/lo, layout [b*NH+h][t][64]
__device__ __align__(256) __nv_bfloat16 g_qh[BB*NH*TT*HD], g_ql[BB*NH*TT*HD];
__device__ __align__(256) __nv_bfloat16 g_kh[BB*NH*TT*HD], g_kl[BB*NH*TT*HD];
__device__ __align__(256) __nv_bfloat16 g_vh[BB*NH*TT*VD], g_vl[BB*NH*TT*VD];

// bf16 triple-split buffers for projections: A' = [hi|hi|lo], B' = [hi|lo|hi]
__device__ __align__(256) __nv_bfloat16 g_xq [MTOT * 3 * DD];
__device__ __align__(256) __nv_bfloat16 g_Wq3[DD * 3 * DD];
__device__ __align__(256) __nv_bfloat16 g_Wa3[KVA_PAD * 3 * DD];
__device__ __align__(256) __nv_bfloat16 g_Wb3[KVB_N * 3 * RR];
__device__ __align__(256) __nv_bfloat16 g_Wo3[DD * 3 * DD];
__device__ __align__(256) __nv_bfloat16 g_l3 [MTOT * 3 * RR];
__device__ __align__(256) __nv_bfloat16 g_a3 [MTOT * 3 * DD];

// ======================= small helpers =======================
__device__ __forceinline__ uint32_t smem_u32(const void* p) {
    uint32_t a;
    asm("{ .reg .u64 t; cvta.to.shared.u64 t, %1; cvt.u32.u64 %0, t; }" : "=r"(a) : "l"(p));
    return a;
}
__device__ __forceinline__ void mma16816(float* c, const uint32_t* a, const uint32_t* b) {
    asm volatile("mma.sync.aligned.m16n8k16.row.col.f32.bf16.bf16.f32 "
        "{%0,%1,%2,%3}, {%4,%5,%6,%7}, {%8,%9}, {%0,%1,%2,%3};"
        : "+f"(c[0]), "+f"(c[1]), "+f"(c[2]), "+f"(c[3])
        : "r"(a[0]), "r"(a[1]), "r"(a[2]), "r"(a[3]), "r"(b[0]), "r"(b[1]));
}
__device__ __forceinline__ void ldsm4(uint32_t* r, uint32_t addr) {
    asm volatile("ldmatrix.sync.aligned.m8n8.x4.shared.b16 {%0,%1,%2,%3}, [%4];"
        : "=r"(r[0]), "=r"(r[1]), "=r"(r[2]), "=r"(r[3]) : "r"(addr));
}
__device__ __forceinline__ void ldsm4t(uint32_t* r, uint32_t addr) {
    asm volatile("ldmatrix.sync.aligned.m8n8.x4.trans.shared.b16 {%0,%1,%2,%3}, [%4];"
        : "=r"(r[0]), "=r"(r[1]), "=r"(r[2]), "=r"(r[3]) : "r"(addr));
}
__device__ __forceinline__ uint32_t packbf(float lo, float hi) {
    uint32_t d;
    asm("cvt.rn.bf16x2.f32 %0, %1, %2;" : "=r"(d) : "f"(hi), "f"(lo));
    return d;
}

// ======================= fp32 -> bf16 triple-split convert =======================
__global__ __launch_bounds__(256) void cvt_triple(
    const float* __restrict__ s, __nv_bfloat16* __restrict__ o,
    int K, int npad_elems, int nreal_elems, int mode)
{
    int stride = gridDim.x * blockDim.x * 4;
    for (int e = (blockIdx.x * blockDim.x + threadIdx.x) * 4; e < npad_elems; e += stride) {
        float4 v = (e < nreal_elems) ? *(const float4*)(s + e)
                                     : make_float4(0.f, 0.f, 0.f, 0.f);
        __nv_bfloat16 h[4], l[4];
        h[0] = __float2bfloat16(v.x); l[0] = __float2bfloat16(v.x - __bfloat162float(h[0]));
        h[1] = __float2bfloat16(v.y); l[1] = __float2bfloat16(v.y - __bfloat162float(h[1]));
        h[2] = __float2bfloat16(v.z); l[2] = __float2bfloat16(v.z - __bfloat162float(h[2]));
        h[3] = __float2bfloat16(v.w); l[3] = __float2bfloat16(v.w - __bfloat162float(h[3]));
        int row = e / K, col = e % K;
        __nv_bfloat16* base = o + (size_t)row * (3 * K) + col;
        __nv_bfloat162 hp0(h[0], h[1]), hp1(h[2], h[3]);
        __nv_bfloat162 lp0(l[0], l[1]), lp1(l[2], l[3]);
        ((__nv_bfloat162*)(base))[0] = hp0;           ((__nv_bfloat162*)(base))[1] = hp1;
        if (mode == 0) {
            ((__nv_bfloat162*)(base + K))[0] = hp0;   ((__nv_bfloat162*)(base + K))[1] = hp1;
            ((__nv_bfloat162*)(base + 2*K))[0] = lp0; ((__nv_bfloat162*)(base + 2*K))[1] = lp1;
        } else {
            ((__nv_bfloat162*)(base + K))[0] = lp0;   ((__nv_bfloat162*)(base + K))[1] = lp1;
            ((__nv_bfloat162*)(base + 2*K))[0] = hp0; ((__nv_bfloat162*)(base + 2*K))[1] = hp1;
        }
    }
}

// ======================= HMMA GEMM (unchanged from R3) =======================
#define GPAD 40
#define GTILE_B (128 * GPAD * 2)
#define GBUF_B  (2 * GTILE_B)

__global__ __launch_bounds__(256) void hmma_gemm(
    const __nv_bfloat16* __restrict__ Ap, const __nv_bfloat16* __restrict__ Bp,
    float* __restrict__ C, int Kp, int Nreal, int ldc)
{
    __shared__ __align__(16) char smem[2 * GBUF_B];

    const int tid = threadIdx.x, wid = tid >> 5, lane = tid & 31;
    const int warp_m = wid >> 2, warp_n = wid & 3;
    const int m0 = blockIdx.y * 128, n0 = blockIdx.x * 128;
    uint32_t smem_base = smem_u32(smem);

    const char* Abase = (const char*)(Ap + (size_t)m0 * Kp);
    const char* Bbase = (const char*)(Bp + (size_t)n0 * Kp);
    const size_t ldbytes = (size_t)Kp * 2;
    const int nch = Kp >> 5;

    float acc[4][4][4];
    #pragma unroll
    for (int i = 0; i < 4; i++)
        #pragma unroll
        for (int j = 0; j < 4; j++)
            #pragma unroll
            for (int e = 0; e < 4; e++) acc[i][j][e] = 0.f;

    auto load_chunk = [&](int ch, int buf) {
        const int k0b = (ch << 5) * 2;
        #pragma unroll
        for (int it = 0; it < 4; it++) {
            int i = tid + it * 256;
            int mat = i >> 9, rem = i & 511;
            int row = rem >> 2, seg = rem & 3;
            const char* src = (mat ? Bbase : Abase) + (size_t)row * ldbytes + k0b + seg * 16;
            uint32_t dst = smem_base + buf * GBUF_B + mat * GTILE_B
                         + (row * GPAD + seg * 8) * 2;
            asm volatile("cp.async.cg.shared.global [%0], [%1], 16;" :: "r"(dst), "l"(src));
        }
        asm volatile("cp.async.commit_group;");
    };

    auto compute_chunk = [&](int buf) {
        const uint32_t smA = smem_base + buf * GBUF_B;
        const uint32_t smB = smA + GTILE_B;
        const int lm = lane & 15, lh = lane >> 4;
        const int g = lane >> 3, r = lane & 7;
        #pragma unroll
        for (int k16 = 0; k16 < 2; k16++) {
            uint32_t a[4][4];
            #pragma unroll
            for (int fm = 0; fm < 4; fm++) {
                uint32_t addr = smA + ((warp_m * 64 + fm * 16 + lm) * GPAD
                                       + k16 * 16 + lh * 8) * 2;
                ldsm4(a[fm], addr);
            }
            uint32_t b[4][2];
            #pragma unroll
            for (int fp = 0; fp < 2; fp++) {
                int row = warp_n * 32 + fp * 16 + ((g >> 1) << 3) + r;
                int col = (g & 1) * 8 + k16 * 16;
                uint32_t addr = smB + (row * GPAD + col) * 2;
                uint32_t t4[4];
                ldsm4(t4, addr);
                b[fp*2][0] = t4[0]; b[fp*2][1] = t4[1];
                b[fp*2+1][0] = t4[2]; b[fp*2+1][1] = t4[3];
            }
            #pragma unroll
            for (int fm = 0; fm < 4; fm++)
                #pragma unroll
                for (int fn = 0; fn < 4; fn++)
                    mma16816(acc[fm][fn], a[fm], b[fn]);
        }
    };

    load_chunk(0, 0);
    asm volatile("cp.async.wait_group 0;");
    __syncthreads();

    for (int ch = 0; ch < nch; ch++) {
        const int buf = ch & 1;
        if (ch + 1 < nch) load_chunk(ch + 1, buf ^ 1);
        compute_chunk(buf);
        asm volatile("cp.async.wait_group 0;");
        __syncthreads();
    }

    const int r4 = lane >> 2, c2 = (lane & 3) * 2;
    #pragma unroll
    for (int fm = 0; fm < 4; fm++) {
        #pragma unroll
        for (int fn = 0; fn < 4; fn++) {
            int m = m0 + warp_m * 64 + fm * 16 + r4;
            int n = n0 + warp_n * 32 + fn * 8 + c2;
            if (n < Nreal) {
                *(float2*)&C[(size_t)m * ldc + n] =
                    make_float2(acc[fm][fn][0], acc[fm][fn][1]);
                *(float2*)&C[(size_t)(m + 8) * ldc + n] =
                    make_float2(acc[fm][fn][2], acc[fm][fn][3]);
            }
        }
    }
}

// ---------------- q post: RMS norm + RoPE -> bf16 hi/lo [bh][t][d] ----------------
__global__ __launch_bounds__(64) void q_post_kernel(
    const float* __restrict__ cosp, const float* __restrict__ sinp,
    const float* __restrict__ qw)
{
    int bid = blockIdx.x;
    int h   = bid & (NH - 1);
    int bt  = bid >> 4;
    int t   = bt & (TT - 1);
    int b   = bt >> 11;
    int d   = threadIdx.x;

    float v = g_qraw[(size_t)bt * (NH * HD) + h * HD + d];
    float ss = v * v;
    #pragma unroll
    for (int o = 16; o; o >>= 1) ss += __shfl_xor_sync(~0u, ss, o);
    __shared__ float red[2];
    if ((threadIdx.x & 31) == 0) red[threadIdx.x >> 5] = ss;
    __syncthreads();
    float tot = red[0] + red[1];
    float norm = rsqrtf(tot * (1.0f / HD) + 1e-6f);
    float qn = v * norm * qw[d];

    float pv = __shfl_xor_sync(~0u, qn, 8);
    if (d >= NOPE) {
        int i = d & 7;
        float c = cosp[t * 8 + i], s = sinp[t * 8 + i];
        qn = (d < NOPE + 8) ? (qn * c - pv * s) : (qn * c + pv * s);
    }
    size_t idx = (((size_t)(b * NH + h)) * TT + t) * HD + d;
    __nv_bfloat16 hh = __float2bfloat16(qn);
    g_qh[idx] = hh;
    g_ql[idx] = __float2bfloat16(qn - __bfloat162float(hh));
}

// ---------------- kv_a post ----------------
__global__ __launch_bounds__(128) void kva_post_kernel(
    const float* __restrict__ cosp, const float* __restrict__ sinp,
    const float* __restrict__ kvaw)
{
    int bt = blockIdx.x;
    int t  = bt & (TT - 1);
    int tid = threadIdx.x;

    float v = g_kva[(size_t)bt * KVA_N + tid];
    float ss = v * v;
    #pragma unroll
    for (int o = 16; o; o >>= 1) ss += __shfl_xor_sync(~0u, ss, o);
    __shared__ float red[4];
    if ((tid & 31) == 0) red[tid >> 5] = ss;
    __syncthreads();
    float tot = red[0] + red[1] + red[2] + red[3];
    float norm = rsqrtf(tot * (1.0f / RR) + 1e-6f);
    g_lat[(size_t)bt * RR + tid] = v * norm * kvaw[tid];

    if (tid < 32) {
        float rv = (tid < ROPED) ? g_kva[(size_t)bt * KVA_N + RR + tid] : 0.f;
        float pv = __shfl_xor_sync(~0u, rv, 8);
        if (tid < ROPED) {
            int i = tid & 7;
            float c = cosp[t * 8 + i], s = sinp[t * 8 + i];
            float outv = (tid < 8) ? (rv * c - pv * s) : (rv * c + pv * s);
            g_krope[(size_t)bt * ROPED + tid] = outv;
        }
    }
}

// ---------------- assemble k/v -> bf16 hi/lo [bh][t][d] ----------------
__global__ __launch_bounds__(256) void assemble_kernel()
{
    const int NTOT = BB * NH * TT * HD;
    for (int idx = blockIdx.x * blockDim.x + threadIdx.x; idx < NTOT;
         idx += gridDim.x * blockDim.x) {
        int d = idx & 63;
        int t = (idx >> 6) & (TT - 1);
        int h = (idx >> 17) & (NH - 1);
        int b = idx >> 21;
        size_t bt = (size_t)b * TT + t;
        float kv;
        if (d < NOPE) kv = g_kvb[bt * KVB_N + h * (NOPE + VD) + d];
        else          kv = g_krope[bt * ROPED + (d - NOPE)];
        float vv = g_kvb[bt * KVB_N + h * (NOPE + VD) + NOPE + d];
        __nv_bfloat16 kh = __float2bfloat16(kv);
        __nv_bfloat16 vh = __float2bfloat16(vv);
        g_kh[idx] = kh; g_kl[idx] = __float2bfloat16(kv - __bfloat162float(kh));
        g_vh[idx] = vh; g_vl[idx] = __float2bfloat16(vv - __bfloat162float(vh));
    }
}

// ---------------- flash attention on mma.sync (hi/lo 3-term) ----------------
// grid (T/128, B*NH), 256 threads, 8 warps x m16. K/V tiles of 64 rows.
#define FPAD 72

__global__ __launch_bounds__(256) void flash_mma()
{
    __shared__ __align__(16) __nv_bfloat16 sm[4 * 64 * FPAD];  // 36864 B

    const int tid = threadIdx.x, wid = tid >> 5, lane = tid & 31;
    const int bh = blockIdx.y;
    const int b = bh >> 4, h = bh & (NH - 1);
    const int qb = blockIdx.x * 128;
    const uint32_t sb = smem_u32(sm);

    const int lm = lane & 15, lh = lane >> 4;
    const int g = lane >> 3, r8 = lane & 7;
    const int r4 = lane >> 2, c2 = (lane & 3) * 2;

    // ---- stage Q (128 rows hi + lo) into smem, ldmatrix into regs ----
    {
        const __nv_bfloat16* qhp = g_qh + ((size_t)bh * TT + qb) * HD;
        const __nv_bfloat16* qlp = g_ql + ((size_t)bh * TT + qb) * HD;
        for (int i = tid; i < 128 * 8; i += 256) {
            int r = i >> 3, s = i & 7;
            *(uint4*)(sm + r * FPAD + s * 8) = *(const uint4*)(qhp + r * 64 + s * 8);
            *(uint4*)(sm + 128 * FPAD + r * FPAD + s * 8) = *(const uint4*)(qlp + r * 64 + s * 8);
        }
    }
    __syncthreads();

    uint32_t qh[4][4], ql[4][4];
    #pragma unroll
    for (int ks = 0; ks < 4; ks++) {
        uint32_t addr = sb + ((wid * 16 + lm) * FPAD + ks * 16 + lh * 8) * 2;
        ldsm4(qh[ks], addr);
        ldsm4(ql[ks], addr + 128 * FPAD * 2);
    }

    float o[8][4];
    #pragma unroll
    for (int i = 0; i < 8; i++)
        #pragma unroll
        for (int e = 0; e < 4; e++) o[i][e] = 0.f;
    float mrow[2] = { -1e30f, -1e30f };
    float lsum[2] = { 0.f, 0.f };

    const __nv_bfloat16* khb = g_kh + (size_t)bh * TT * HD;
    const __nv_bfloat16* klb = g_kl + (size_t)bh * TT * HD;
    const __nv_bfloat16* vhb = g_vh + (size_t)bh * TT * VD;
    const __nv_bfloat16* vlb = g_vl + (size_t)bh * TT * VD;

    const int ntiles = blockIdx.x * 2 + 2;
    const float scale = 0.125f;
    const int q0 = qb + wid * 16 + r4;   // this thread's first q row
    const int q1 = q0 + 8;

    __nv_bfloat16* sKh = sm;
    __nv_bfloat16* sKl = sm + 64 * FPAD;
    __nv_bfloat16* sVh = sm + 2 * 64 * FPAD;
    __nv_bfloat16* sVl = sm + 3 * 64 * FPAD;
    const uint32_t oKh = 0, oKl = 64 * FPAD * 2, oVh = 2 * 64 * FPAD * 2, oVl = 3 * 64 * FPAD * 2;

    for (int it = 0; it < ntiles; it++) {
        const int j0 = it * 64;
        __syncthreads();   // previous tile fully consumed (and Q frags loaded)
        for (int i = tid; i < 64 * 8; i += 256) {
            int r = i >> 3, s = i & 7;
            size_t gsrc = (size_t)(j0 + r) * 64 + s * 8;
            int dsh = r * FPAD + s * 8;
            *(uint4*)(sKh + dsh) = *(const uint4*)(khb + gsrc);
            *(uint4*)(sKl + dsh) = *(const uint4*)(klb + gsrc);
            *(uint4*)(sVh + dsh) = *(const uint4*)(vhb + gsrc);
            *(uint4*)(sVl + dsh) = *(const uint4*)(vlb + gsrc);
        }
        __syncthreads();

        // ---- S = Q K^T (3-term) ----
        float s[8][4];
        #pragma unroll
        for (int i = 0; i < 8; i++)
            #pragma unroll
            for (int e = 0; e < 4; e++) s[i][e] = 0.f;

        #pragma unroll
        for (int fp = 0; fp < 4; fp++) {
            const int krow = fp * 16 + ((g >> 1) << 3) + r8;
            const int kcol = (g & 1) * 8;
            #pragma unroll
            for (int ks = 0; ks < 4; ks++) {
                uint32_t addr = sb + oKh + (krow * FPAD + kcol + ks * 16) * 2;
                uint32_t bhf[4], blf[4];
                ldsm4(bhf, addr);
                ldsm4(blf, addr + (oKl - oKh));
                uint32_t bh0[2] = { bhf[0], bhf[1] }, bh1[2] = { bhf[2], bhf[3] };
                uint32_t bl0[2] = { blf[0], blf[1] }, bl1[2] = { blf[2], blf[3] };
                mma16816(s[fp*2],   qh[ks], bh0);
                mma16816(s[fp*2],   qh[ks], bl0);
                mma16816(s[fp*2],   ql[ks], bh0);
                mma16816(s[fp*2+1], qh[ks], bh1);
                mma16816(s[fp*2+1], qh[ks], bl1);
                mma16816(s[fp*2+1], ql[ks], bh1);
            }
        }

        // scale + causal mask
        const bool need_mask = (it >= ntiles - 2);
        #pragma unroll
        for (int fn = 0; fn < 8; fn++) {
            #pragma unroll
            for (int e = 0; e < 4; e++) {
                float x = s[fn][e] * scale;
                if (need_mask) {
                    int kv = j0 + fn * 8 + c2 + (e & 1);
                    int qq = (e < 2) ? q0 : q1;
                    if (kv > qq) x = -1e30f;
                }
                s[fn][e] = x;
            }
        }

        // row max (2 rows per thread), quad reduce
        float tm0 = -1e30f, tm1 = -1e30f;
        #pragma unroll
        for (int fn = 0; fn < 8; fn++) {
            tm0 = fmaxf(tm0, fmaxf(s[fn][0], s[fn][1]));
            tm1 = fmaxf(tm1, fmaxf(s[fn][2], s[fn][3]));
        }
        tm0 = fmaxf(tm0, __shfl_xor_sync(~0u, tm0, 1));
        tm0 = fmaxf(tm0, __shfl_xor_sync(~0u, tm0, 2));
        tm1 = fmaxf(tm1, __shfl_xor_sync(~0u, tm1, 1));
        tm1 = fmaxf(tm1, __shfl_xor_sync(~0u, tm1, 2));

        float mn0 = fmaxf(mrow[0], tm0), mn1 = fmaxf(mrow[1], tm1);
        float cr0 = __expf(mrow[0] - mn0), cr1 = __expf(mrow[1] - mn1);
        mrow[0] = mn0; mrow[1] = mn1;
        lsum[0] *= cr0; lsum[1] *= cr1;
        #pragma unroll
        for (int fn = 0; fn < 8; fn++) {
            o[fn][0] *= cr0; o[fn][1] *= cr0;
            o[fn][2] *= cr1; o[fn][3] *= cr1;
        }

        // p = exp(s - m); accumulate row sums
        #pragma unroll
        for (int fn = 0; fn < 8; fn++) {
            s[fn][0] = __expf(s[fn][0] - mn0);
            s[fn][1] = __expf(s[fn][1] - mn0);
            s[fn][2] = __expf(s[fn][2] - mn1);
            s[fn][3] = __expf(s[fn][3] - mn1);
            lsum[0] += s[fn][0] + s[fn][1];
            lsum[1] += s[fn][2] + s[fn][3];
        }

        // ---- O += P V (3-term, P hi/lo) ----
        #pragma unroll
        for (int ks = 0; ks < 4; ks++) {
            float p00 = s[ks*2][0],  p01 = s[ks*2][1],  p02 = s[ks*2][2],  p03 = s[ks*2][3];
            float p10 = s[ks*2+1][0],p11 = s[ks*2+1][1],p12 = s[ks*2+1][2],p13 = s[ks*2+1][3];
            uint32_t aph[4], apl[4];
            aph[0] = packbf(p00, p01); aph[1] = packbf(p02, p03);
            aph[2] = packbf(p10, p11); aph[3] = packbf(p12, p13);
            // lo residuals
            float h00 = __bfloat162float(__float2bfloat16(p00));
            float h01 = __bfloat162float(__float2bfloat16(p01));
            float h02 = __bfloat162float(__float2bfloat16(p02));
            float h03 = __bfloat162float(__float2bfloat16(p03));
            float h10 = __bfloat162float(__float2bfloat16(p10));
            float h11 = __bfloat162float(__float2bfloat16(p11));
            float h12 = __bfloat162float(__float2bfloat16(p12));
            float h13 = __bfloat162float(__float2bfloat16(p13));
            apl[0] = packbf(p00 - h00, p01 - h01);
            apl[1] = packbf(p02 - h02, p03 - h03);
            apl[2] = packbf(p10 - h10, p11 - h11);
            apl[3] = packbf(p12 - h12, p13 - h13);

            const int vrow = ks * 16 + (g & 1) * 8 + r8;
            #pragma unroll
            for (int np = 0; np < 4; np++) {
                const int vcol = np * 16 + lh * 8;
                uint32_t addr = sb + oVh + (vrow * FPAD + vcol) * 2;
                uint32_t bvh[4], bvl[4];
                ldsm4t(bvh, addr);
                ldsm4t(bvl, addr + (oVl - oVh));
                uint32_t bh0[2] = { bvh[0], bvh[1] }, bh1[2] = { bvh[2], bvh[3] };
                uint32_t bl0[2] = { bvl[0], bvl[1] }, bl1[2] = { bvl[2], bvl[3] };
                mma16816(o[np*2],   aph, bh0);
                mma16816(o[np*2],   aph, bl0);
                mma16816(o[np*2],   apl, bh0);
                mma16816(o[np*2+1], aph, bh1);
                mma16816(o[np*2+1], aph, bl1);
                mma16816(o[np*2+1], apl, bh1);
            }
        }
    }

    // final row-sum reduce + write
    lsum[0] += __shfl_xor_sync(~0u, lsum[0], 1);
    lsum[0] += __shfl_xor_sync(~0u, lsum[0], 2);
    lsum[1] += __shfl_xor_sync(~0u, lsum[1], 1);
    lsum[1] += __shfl_xor_sync(~0u, lsum[1], 2);
    const float inv0 = 1.f / lsum[0], inv1 = 1.f / lsum[1];

    float* ob0 = g_ao + ((size_t)(b * TT + q0)) * (NH * VD) + h * VD;
    float* ob1 = g_ao + ((size_t)(b * TT + q1)) * (NH * VD) + h * VD;
    #pragma unroll
    for (int fn = 0; fn < 8; fn++) {
        *(float2*)(ob0 + fn * 8 + c2) = make_float2(o[fn][0] * inv0, o[fn][1] * inv0);
        *(float2*)(ob1 + fn * 8 + c2) = make_float2(o[fn][2] * inv1, o[fn][3] * inv1);
    }
}

// ---------------- launch ----------------
static void* sym_addr(const void* symbol) {
    void* p = nullptr;
    cudaGetSymbolAddress(&p, symbol);
    return p;
}

static void launch_cvt(const float* src, void* o, int K, int npad_rows, int nreal_rows, int mode) {
    int npad_elems = npad_rows * K;
    int blocks = (npad_elems / 4 + 255) / 256;
    if (blocks > 16384) blocks = 16384;
    cvt_triple<<<blocks, 256>>>(src, (__nv_bfloat16*)o, K, npad_elems, nreal_rows * K, mode);
}

extern "C" void kernel_launch(void* const* d_in, const int* in_sizes, int n_in,
                              void* d_out, int out_size)
{
    const float* x    = (const float*)d_in[0];
    const float* cosp = (const float*)d_in[1];
    const float* sinp = (const float*)d_in[2];
    const float* Wq   = (const float*)d_in[3];
    const float* qw   = (const float*)d_in[4];
    const float* Wkva = (const float*)d_in[5];
    const float* kvaw = (const float*)d_in[6];
    const float* Wkvb = (const float*)d_in[7];
    const float* Wo   = (const float*)d_in[8];
    float* out = (float*)d_out;

    float* qraw = (float*)sym_addr(g_qraw);
    float* kva  = (float*)sym_addr(g_kva);
    float* lat  = (float*)sym_addr(g_lat);
    float* kvb  = (float*)sym_addr(g_kvb);
    float* ao   = (float*)sym_addr(g_ao);

    __nv_bfloat16* xq  = (__nv_bfloat16*)sym_addr(g_xq);
    __nv_bfloat16* wq3 = (__nv_bfloat16*)sym_addr(g_Wq3);
    __nv_bfloat16* wa3 = (__nv_bfloat16*)sym_addr(g_Wa3);
    __nv_bfloat16* wb3 = (__nv_bfloat16*)sym_addr(g_Wb3);
    __nv_bfloat16* wo3 = (__nv_bfloat16*)sym_addr(g_Wo3);
    __nv_bfloat16* l3  = (__nv_bfloat16*)sym_addr(g_l3);
    __nv_bfloat16* a3  = (__nv_bfloat16*)sym_addr(g_a3);

    // 0) triple-split conversions
    launch_cvt(x,    xq,  DD, MTOT,    MTOT,  0);
    launch_cvt(Wq,   wq3, DD, DD,      DD,    1);
    launch_cvt(Wkva, wa3, DD, KVA_PAD, KVA_N, 1);
    launch_cvt(Wkvb, wb3, RR, KVB_N,   KVB_N, 1);
    launch_cvt(Wo,   wo3, DD, DD,      DD,    1);

    // 1) q projection + kv_a projection
    {
        dim3 g(DD / 128, MTOT / 128);
        hmma_gemm<<<g, 256>>>(xq, wq3, qraw, 3 * DD, NH * HD, NH * HD);
    }
    {
        dim3 g(KVA_PAD / 128, MTOT / 128);
        hmma_gemm<<<g, 256>>>(xq, wa3, kva, 3 * DD, KVA_N, KVA_N);
    }

    // 2) norms + rope (emit bf16 hi/lo attention operands)
    q_post_kernel<<<MTOT * NH, 64>>>(cosp, sinp, qw);
    kva_post_kernel<<<MTOT, 128>>>(cosp, sinp, kvaw);

    // 3) kv_b projection + assemble
    launch_cvt(lat, l3, RR, MTOT, MTOT, 0);
    {
        dim3 g(KVB_N / 128, MTOT / 128);
        hmma_gemm<<<g, 256>>>(l3, wb3, kvb, 3 * RR, KVB_N, KVB_N);
    }
    assemble_kernel<<<4096, 256>>>();

    // 4) flash attention on tensor cores
    {
        dim3 g(TT / 128, BB * NH);
        flash_mma<<<g, 256>>>();
    }

    // 5) output projection
    launch_cvt(ao, a3, DD, MTOT, MTOT, 0);
    {
        dim3 g(DD / 128, MTOT / 128);
        hmma_gemm<<<g, 256>>>(a3, wo3, out, 3 * DD, DD, DD);
    }
}

// round 5
// speedup vs baseline: 3.5457x; 1.4084x over previous
#include <cuda_runtime.h>
#include <cuda_fp16.h>
#include <math.h>
#include <cstdint>

#define BB 2
#define TT 2048
#define DD 1024
#define NH 16
#define HD 64      // NOPE_D + ROPE_D
#define NOPE 48
#define ROPED 16
#define RR 128
#define VD 64
#define KVB_N (NH * (NOPE + VD))   // 1792
#define KVA_N (RR + ROPED)         // 144
#define KVA_PAD 256
#define MTOT (BB * TT)             // 4096

// ---------------- scratch (device globals; no allocs allowed) ----------------
__device__ float g_qraw[MTOT * NH * HD];
__device__ float g_kva [MTOT * KVA_N];
__device__ float g_lat [MTOT * RR];
__device__ float g_krope[MTOT * ROPED];
__device__ float g_kvb [MTOT * KVB_N];
__device__ float g_ao  [MTOT * NH * VD];

// attention operands fp16, layout [b*NH+h][t][64]
__device__ __align__(256) __half g_qh[BB*NH*TT*HD], g_ql[BB*NH*TT*HD];
__device__ __align__(256) __half g_kh[BB*NH*TT*HD], g_kl[BB*NH*TT*HD];
__device__ __align__(256) __half g_vh[BB*NH*TT*VD];

// fp16 GEMM operands (A hi only; B hi+lo)
__device__ __align__(256) __half g_xh [MTOT * DD];
__device__ __align__(256) __half g_Wqh[DD * DD],      g_Wql[DD * DD];
__device__ __align__(256) __half g_Wah[KVA_PAD * DD], g_Wal[KVA_PAD * DD];
__device__ __align__(256) __half g_Wbh[KVB_N * RR],   g_Wbl[KVB_N * RR];
__device__ __align__(256) __half g_Woh[DD * DD],      g_Wol[DD * DD];
__device__ __align__(256) __half g_lth[MTOT * RR];
__device__ __align__(256) __half g_aoh[MTOT * DD];

// ======================= helpers =======================
__device__ __forceinline__ uint32_t smem_u32(const void* p) {
    uint32_t a;
    asm("{ .reg .u64 t; cvta.to.shared.u64 t, %1; cvt.u32.u64 %0, t; }" : "=r"(a) : "l"(p));
    return a;
}
__device__ __forceinline__ void mma16816(float* c, const uint32_t* a, const uint32_t* b) {
    asm volatile("mma.sync.aligned.m16n8k16.row.col.f32.f16.f16.f32 "
        "{%0,%1,%2,%3}, {%4,%5,%6,%7}, {%8,%9}, {%0,%1,%2,%3};"
        : "+f"(c[0]), "+f"(c[1]), "+f"(c[2]), "+f"(c[3])
        : "r"(a[0]), "r"(a[1]), "r"(a[2]), "r"(a[3]), "r"(b[0]), "r"(b[1]));
}
__device__ __forceinline__ void ldsm4(uint32_t* r, uint32_t addr) {
    asm volatile("ldmatrix.sync.aligned.m8n8.x4.shared.b16 {%0,%1,%2,%3}, [%4];"
        : "=r"(r[0]), "=r"(r[1]), "=r"(r[2]), "=r"(r[3]) : "r"(addr));
}
__device__ __forceinline__ void ldsm4t(uint32_t* r, uint32_t addr) {
    asm volatile("ldmatrix.sync.aligned.m8n8.x4.trans.shared.b16 {%0,%1,%2,%3}, [%4];"
        : "=r"(r[0]), "=r"(r[1]), "=r"(r[2]), "=r"(r[3]) : "r"(addr));
}
__device__ __forceinline__ uint32_t packh(float lo, float hi) {
    uint32_t d;
    asm("cvt.rn.f16x2.f32 %0, %1, %2;" : "=r"(d) : "f"(hi), "f"(lo));
    return d;
}

// ======================= conversions =======================
__global__ __launch_bounds__(256) void cvt_h(
    const float* __restrict__ s, __half* __restrict__ d, int npad, int nreal)
{
    int stride = gridDim.x * blockDim.x * 4;
    for (int e = (blockIdx.x * blockDim.x + threadIdx.x) * 4; e < npad; e += stride) {
        float4 v = (e < nreal) ? *(const float4*)(s + e) : make_float4(0.f,0.f,0.f,0.f);
        __half2 p0(__float2half(v.x), __float2half(v.y));
        __half2 p1(__float2half(v.z), __float2half(v.w));
        ((__half2*)(d + e))[0] = p0;
        ((__half2*)(d + e))[1] = p1;
    }
}

__global__ __launch_bounds__(256) void cvt_hl(
    const float* __restrict__ s, __half* __restrict__ dh, __half* __restrict__ dl,
    int npad, int nreal)
{
    int stride = gridDim.x * blockDim.x * 4;
    for (int e = (blockIdx.x * blockDim.x + threadIdx.x) * 4; e < npad; e += stride) {
        float4 v = (e < nreal) ? *(const float4*)(s + e) : make_float4(0.f,0.f,0.f,0.f);
        __half h0 = __float2half(v.x), h1 = __float2half(v.y);
        __half h2 = __float2half(v.z), h3 = __float2half(v.w);
        ((__half2*)(dh + e))[0] = __half2(h0, h1);
        ((__half2*)(dh + e))[1] = __half2(h2, h3);
        __half l0 = __float2half(v.x - __half2float(h0));
        __half l1 = __float2half(v.y - __half2float(h1));
        __half l2 = __float2half(v.z - __half2float(h2));
        __half l3 = __float2half(v.w - __half2float(h3));
        ((__half2*)(dl + e))[0] = __half2(l0, l1);
        ((__half2*)(dl + e))[1] = __half2(l2, l3);
    }
}

// ======================= 2-term fp16 GEMM =======================
// C[M,Nreal] = Ah[M,K] @ (Bh+Bl)[Npad,K]^T.  Tile 128x128, BK=32.
#define GPAD 40
#define GTILE_B (128 * GPAD * 2)     // 10240
#define GBUF_B  (3 * GTILE_B)        // 30720 (A, Bh, Bl)

__global__ __launch_bounds__(256) void gemm2t(
    const __half* __restrict__ Ah, const __half* __restrict__ Bh,
    const __half* __restrict__ Bl, float* __restrict__ C,
    int K, int Nreal, int ldc)
{
    extern __shared__ __align__(16) char smem[];   // 2 * GBUF_B = 61440

    const int tid = threadIdx.x, wid = tid >> 5, lane = tid & 31;
    const int warp_m = wid >> 2, warp_n = wid & 3;
    const int m0 = blockIdx.y * 128, n0 = blockIdx.x * 128;
    uint32_t smem_base = smem_u32(smem);

    const char* base[3] = { (const char*)(Ah + (size_t)m0 * K),
                            (const char*)(Bh + (size_t)n0 * K),
                            (const char*)(Bl + (size_t)n0 * K) };
    const size_t ldbytes = (size_t)K * 2;
    const int nch = K >> 5;

    float acc[4][4][4];
    #pragma unroll
    for (int i = 0; i < 4; i++)
        #pragma unroll
        for (int j = 0; j < 4; j++)
            #pragma unroll
            for (int e = 0; e < 4; e++) acc[i][j][e] = 0.f;

    auto load_chunk = [&](int ch, int buf) {
        const int k0b = (ch << 5) * 2;
        #pragma unroll
        for (int it = 0; it < 6; it++) {
            int i = tid + it * 256;          // 0..1535
            int mat = i >> 9, rem = i & 511;
            int row = rem >> 2, seg = rem & 3;
            const char* src = base[mat] + (size_t)row * ldbytes + k0b + seg * 16;
            uint32_t dst = smem_base + buf * GBUF_B + mat * GTILE_B
                         + (row * GPAD + seg * 8) * 2;
            asm volatile("cp.async.cg.shared.global [%0], [%1], 16;" :: "r"(dst), "l"(src));
        }
        asm volatile("cp.async.commit_group;");
    };

    auto compute_chunk = [&](int buf) {
        const uint32_t smA  = smem_base + buf * GBUF_B;
        const uint32_t smBh = smA + GTILE_B;
        const uint32_t smBl = smBh + GTILE_B;
        const int lm = lane & 15, lh = lane >> 4;
        const int g = lane >> 3, r = lane & 7;
        #pragma unroll
        for (int k16 = 0; k16 < 2; k16++) {
            uint32_t a[4][4];
            #pragma unroll
            for (int fm = 0; fm < 4; fm++) {
                uint32_t addr = smA + ((warp_m * 64 + fm * 16 + lm) * GPAD
                                       + k16 * 16 + lh * 8) * 2;
                ldsm4(a[fm], addr);
            }
            uint32_t bh[4][2], bl[4][2];
            #pragma unroll
            for (int fp = 0; fp < 2; fp++) {
                int row = warp_n * 32 + fp * 16 + ((g >> 1) << 3) + r;
                int off = (row * GPAD + (g & 1) * 8 + k16 * 16) * 2;
                uint32_t t4[4];
                ldsm4(t4, smBh + off);
                bh[fp*2][0]=t4[0]; bh[fp*2][1]=t4[1]; bh[fp*2+1][0]=t4[2]; bh[fp*2+1][1]=t4[3];
                ldsm4(t4, smBl + off);
                bl[fp*2][0]=t4[0]; bl[fp*2][1]=t4[1]; bl[fp*2+1][0]=t4[2]; bl[fp*2+1][1]=t4[3];
            }
            #pragma unroll
            for (int fm = 0; fm < 4; fm++)
                #pragma unroll
                for (int fn = 0; fn < 4; fn++) {
                    mma16816(acc[fm][fn], a[fm], bh[fn]);
                    mma16816(acc[fm][fn], a[fm], bl[fn]);
                }
        }
    };

    load_chunk(0, 0);
    asm volatile("cp.async.wait_group 0;");
    __syncthreads();

    for (int ch = 0; ch < nch; ch++) {
        const int buf = ch & 1;
        if (ch + 1 < nch) load_chunk(ch + 1, buf ^ 1);
        compute_chunk(buf);
        asm volatile("cp.async.wait_group 0;");
        __syncthreads();
    }

    const int r4 = lane >> 2, c2 = (lane & 3) * 2;
    #pragma unroll
    for (int fm = 0; fm < 4; fm++) {
        #pragma unroll
        for (int fn = 0; fn < 4; fn++) {
            int m = m0 + warp_m * 64 + fm * 16 + r4;
            int n = n0 + warp_n * 32 + fn * 8 + c2;
            if (n < Nreal) {
                *(float2*)&C[(size_t)m * ldc + n] =
                    make_float2(acc[fm][fn][0], acc[fm][fn][1]);
                *(float2*)&C[(size_t)(m + 8) * ldc + n] =
                    make_float2(acc[fm][fn][2], acc[fm][fn][3]);
            }
        }
    }
}

// ---------------- q post: RMS norm + RoPE -> fp16 hi/lo [bh][t][d] ----------------
__global__ __launch_bounds__(64) void q_post_kernel(
    const float* __restrict__ cosp, const float* __restrict__ sinp,
    const float* __restrict__ qw)
{
    int bid = blockIdx.x;
    int h   = bid & (NH - 1);
    int bt  = bid >> 4;
    int t   = bt & (TT - 1);
    int b   = bt >> 11;
    int d   = threadIdx.x;

    float v = g_qraw[(size_t)bt * (NH * HD) + h * HD + d];
    float ss = v * v;
    #pragma unroll
    for (int o = 16; o; o >>= 1) ss += __shfl_xor_sync(~0u, ss, o);
    __shared__ float red[2];
    if ((threadIdx.x & 31) == 0) red[threadIdx.x >> 5] = ss;
    __syncthreads();
    float tot = red[0] + red[1];
    float norm = rsqrtf(tot * (1.0f / HD) + 1e-6f);
    float qn = v * norm * qw[d];

    float pv = __shfl_xor_sync(~0u, qn, 8);
    if (d >= NOPE) {
        int i = d & 7;
        float c = cosp[t * 8 + i], s = sinp[t * 8 + i];
        qn = (d < NOPE + 8) ? (qn * c - pv * s) : (qn * c + pv * s);
    }
    size_t idx = (((size_t)(b * NH + h)) * TT + t) * HD + d;
    __half hh = __float2half(qn);
    g_qh[idx] = hh;
    g_ql[idx] = __float2half(qn - __half2float(hh));
}

// ---------------- kv_a post ----------------
__global__ __launch_bounds__(128) void kva_post_kernel(
    const float* __restrict__ cosp, const float* __restrict__ sinp,
    const float* __restrict__ kvaw)
{
    int bt = blockIdx.x;
    int t  = bt & (TT - 1);
    int tid = threadIdx.x;

    float v = g_kva[(size_t)bt * KVA_N + tid];
    float ss = v * v;
    #pragma unroll
    for (int o = 16; o; o >>= 1) ss += __shfl_xor_sync(~0u, ss, o);
    __shared__ float red[4];
    if ((tid & 31) == 0) red[tid >> 5] = ss;
    __syncthreads();
    float tot = red[0] + red[1] + red[2] + red[3];
    float norm = rsqrtf(tot * (1.0f / RR) + 1e-6f);
    g_lat[(size_t)bt * RR + tid] = v * norm * kvaw[tid];

    if (tid < 32) {
        float rv = (tid < ROPED) ? g_kva[(size_t)bt * KVA_N + RR + tid] : 0.f;
        float pv = __shfl_xor_sync(~0u, rv, 8);
        if (tid < ROPED) {
            int i = tid & 7;
            float c = cosp[t * 8 + i], s = sinp[t * 8 + i];
            float outv = (tid < 8) ? (rv * c - pv * s) : (rv * c + pv * s);
            g_krope[(size_t)bt * ROPED + tid] = outv;
        }
    }
}

// ---------------- assemble k (hi/lo) / v (hi) -> [bh][t][d] ----------------
__global__ __launch_bounds__(256) void assemble_kernel()
{
    const int NTOT = BB * NH * TT * HD;
    for (int idx = blockIdx.x * blockDim.x + threadIdx.x; idx < NTOT;
         idx += gridDim.x * blockDim.x) {
        int d = idx & 63;
        int t = (idx >> 6) & (TT - 1);
        int h = (idx >> 17) & (NH - 1);
        int b = idx >> 21;
        size_t bt = (size_t)b * TT + t;
        float kv;
        if (d < NOPE) kv = g_kvb[bt * KVB_N + h * (NOPE + VD) + d];
        else          kv = g_krope[bt * ROPED + (d - NOPE)];
        float vv = g_kvb[bt * KVB_N + h * (NOPE + VD) + NOPE + d];
        __half kh = __float2half(kv);
        g_kh[idx] = kh;
        g_kl[idx] = __float2half(kv - __half2float(kh));
        g_vh[idx] = __float2half(vv);
    }
}

// ---------------- flash attention (fp16: S 3-term, PV 2-term) ----------------
#define FPAD 72

__global__ __launch_bounds__(256) void flash_mma()
{
    __shared__ __align__(16) __half sm[2 * 128 * FPAD];   // 36864 B

    const int tid = threadIdx.x, wid = tid >> 5, lane = tid & 31;
    const int bh = blockIdx.y;
    const int b = bh >> 4, h = bh & (NH - 1);
    const int qtile = gridDim.x - 1 - blockIdx.x;    // longest-first scheduling
    const int qb = qtile * 128;
    const uint32_t sb = smem_u32(sm);

    const int lm = lane & 15, lh = lane >> 4;
    const int g = lane >> 3, r8 = lane & 7;
    const int r4 = lane >> 2, c2 = (lane & 3) * 2;

    // ---- stage Q (hi + lo) into smem, ldmatrix into regs ----
    {
        const __half* qhp = g_qh + ((size_t)bh * TT + qb) * HD;
        const __half* qlp = g_ql + ((size_t)bh * TT + qb) * HD;
        for (int i = tid; i < 128 * 8; i += 256) {
            int r = i >> 3, s = i & 7;
            *(uint4*)(sm + r * FPAD + s * 8) = *(const uint4*)(qhp + r * 64 + s * 8);
            *(uint4*)(sm + 128 * FPAD + r * FPAD + s * 8) = *(const uint4*)(qlp + r * 64 + s * 8);
        }
    }
    __syncthreads();

    uint32_t qh[4][4], ql[4][4];
    #pragma unroll
    for (int ks = 0; ks < 4; ks++) {
        uint32_t addr = sb + ((wid * 16 + lm) * FPAD + ks * 16 + lh * 8) * 2;
        ldsm4(qh[ks], addr);
        ldsm4(ql[ks], addr + 128 * FPAD * 2);
    }

    float o[8][4];
    #pragma unroll
    for (int i = 0; i < 8; i++)
        #pragma unroll
        for (int e = 0; e < 4; e++) o[i][e] = 0.f;
    float mrow[2] = { -1e30f, -1e30f };
    float lsum[2] = { 0.f, 0.f };

    const __half* khb = g_kh + (size_t)bh * TT * HD;
    const __half* klb = g_kl + (size_t)bh * TT * HD;
    const __half* vhb = g_vh + (size_t)bh * TT * VD;

    const int ntiles = qtile * 2 + 2;
    const float scale = 0.125f;
    const int q0 = qb + wid * 16 + r4;
    const int q1 = q0 + 8;

    const uint32_t oKh = 0;
    const uint32_t oKl = 64 * FPAD * 2;
    const uint32_t oVh = 2 * 64 * FPAD * 2;

    for (int it = 0; it < ntiles; it++) {
        const int j0 = it * 64;
        __syncthreads();
        for (int i = tid; i < 64 * 8; i += 256) {
            int r = i >> 3, s = i & 7;
            size_t gsrc = (size_t)(j0 + r) * 64 + s * 8;
            int dsh = r * FPAD + s * 8;
            *(uint4*)(sm + dsh) = *(const uint4*)(khb + gsrc);
            *(uint4*)(sm + 64 * FPAD + dsh) = *(const uint4*)(klb + gsrc);
            *(uint4*)(sm + 2 * 64 * FPAD + dsh) = *(const uint4*)(vhb + gsrc);
        }
        __syncthreads();

        // ---- S = Q K^T (3-term: qh*kh + qh*kl + ql*kh) ----
        float s[8][4];
        #pragma unroll
        for (int i = 0; i < 8; i++)
            #pragma unroll
            for (int e = 0; e < 4; e++) s[i][e] = 0.f;

        #pragma unroll
        for (int fp = 0; fp < 4; fp++) {
            const int krow = fp * 16 + ((g >> 1) << 3) + r8;
            const int kcol = (g & 1) * 8;
            #pragma unroll
            for (int ks = 0; ks < 4; ks++) {
                uint32_t addr = sb + oKh + (krow * FPAD + kcol + ks * 16) * 2;
                uint32_t bhf[4], blf[4];
                ldsm4(bhf, addr);
                ldsm4(blf, addr + (oKl - oKh));
                uint32_t bh0[2] = { bhf[0], bhf[1] }, bh1[2] = { bhf[2], bhf[3] };
                uint32_t bl0[2] = { blf[0], blf[1] }, bl1[2] = { blf[2], blf[3] };
                mma16816(s[fp*2],   qh[ks], bh0);
                mma16816(s[fp*2],   qh[ks], bl0);
                mma16816(s[fp*2],   ql[ks], bh0);
                mma16816(s[fp*2+1], qh[ks], bh1);
                mma16816(s[fp*2+1], qh[ks], bl1);
                mma16816(s[fp*2+1], ql[ks], bh1);
            }
        }

        // scale + causal mask
        const bool need_mask = (it >= ntiles - 2);
        #pragma unroll
        for (int fn = 0; fn < 8; fn++) {
            #pragma unroll
            for (int e = 0; e < 4; e++) {
                float x = s[fn][e] * scale;
                if (need_mask) {
                    int kv = j0 + fn * 8 + c2 + (e & 1);
                    int qq = (e < 2) ? q0 : q1;
                    if (kv > qq) x = -1e30f;
                }
                s[fn][e] = x;
            }
        }

        // online softmax
        float tm0 = -1e30f, tm1 = -1e30f;
        #pragma unroll
        for (int fn = 0; fn < 8; fn++) {
            tm0 = fmaxf(tm0, fmaxf(s[fn][0], s[fn][1]));
            tm1 = fmaxf(tm1, fmaxf(s[fn][2], s[fn][3]));
        }
        tm0 = fmaxf(tm0, __shfl_xor_sync(~0u, tm0, 1));
        tm0 = fmaxf(tm0, __shfl_xor_sync(~0u, tm0, 2));
        tm1 = fmaxf(tm1, __shfl_xor_sync(~0u, tm1, 1));
        tm1 = fmaxf(tm1, __shfl_xor_sync(~0u, tm1, 2));

        float mn0 = fmaxf(mrow[0], tm0), mn1 = fmaxf(mrow[1], tm1);
        float cr0 = __expf(mrow[0] - mn0), cr1 = __expf(mrow[1] - mn1);
        mrow[0] = mn0; mrow[1] = mn1;
        lsum[0] *= cr0; lsum[1] *= cr1;
        #pragma unroll
        for (int fn = 0; fn < 8; fn++) {
            o[fn][0] *= cr0; o[fn][1] *= cr0;
            o[fn][2] *= cr1; o[fn][3] *= cr1;
        }

        #pragma unroll
        for (int fn = 0; fn < 8; fn++) {
            s[fn][0] = __expf(s[fn][0] - mn0);
            s[fn][1] = __expf(s[fn][1] - mn0);
            s[fn][2] = __expf(s[fn][2] - mn1);
            s[fn][3] = __expf(s[fn][3] - mn1);
            lsum[0] += s[fn][0] + s[fn][1];
            lsum[1] += s[fn][2] + s[fn][3];
        }

        // ---- O += P V (2-term: ph*vh + pl*vh) ----
        #pragma unroll
        for (int ks = 0; ks < 4; ks++) {
            float p0[4] = { s[ks*2][0], s[ks*2][1], s[ks*2][2], s[ks*2][3] };
            float p1[4] = { s[ks*2+1][0], s[ks*2+1][1], s[ks*2+1][2], s[ks*2+1][3] };
            uint32_t aph[4], apl[4];
            aph[0] = packh(p0[0], p0[1]); aph[1] = packh(p0[2], p0[3]);
            aph[2] = packh(p1[0], p1[1]); aph[3] = packh(p1[2], p1[3]);
            float h0[4], h1[4];
            #pragma unroll
            for (int e = 0; e < 4; e++) {
                h0[e] = __half2float(__float2half(p0[e]));
                h1[e] = __half2float(__float2half(p1[e]));
            }
            apl[0] = packh(p0[0]-h0[0], p0[1]-h0[1]);
            apl[1] = packh(p0[2]-h0[2], p0[3]-h0[3]);
            apl[2] = packh(p1[0]-h1[0], p1[1]-h1[1]);
            apl[3] = packh(p1[2]-h1[2], p1[3]-h1[3]);

            const int vrow = ks * 16 + (g & 1) * 8 + r8;
            #pragma unroll
            for (int np = 0; np < 4; np++) {
                const int vcol = np * 16 + lh * 8;
                uint32_t addr = sb + oVh + (vrow * FPAD + vcol) * 2;
                uint32_t bvh[4];
                ldsm4t(bvh, addr);
                uint32_t b0[2] = { bvh[0], bvh[1] }, b1[2] = { bvh[2], bvh[3] };
                mma16816(o[np*2],   aph, b0);
                mma16816(o[np*2],   apl, b0);
                mma16816(o[np*2+1], aph, b1);
                mma16816(o[np*2+1], apl, b1);
            }
        }
    }

    lsum[0] += __shfl_xor_sync(~0u, lsum[0], 1);
    lsum[0] += __shfl_xor_sync(~0u, lsum[0], 2);
    lsum[1] += __shfl_xor_sync(~0u, lsum[1], 1);
    lsum[1] += __shfl_xor_sync(~0u, lsum[1], 2);
    const float inv0 = 1.f / lsum[0], inv1 = 1.f / lsum[1];

    float* ob0 = g_ao + ((size_t)(b * TT + q0)) * (NH * VD) + h * VD;
    float* ob1 = g_ao + ((size_t)(b * TT + q1)) * (NH * VD) + h * VD;
    #pragma unroll
    for (int fn = 0; fn < 8; fn++) {
        *(float2*)(ob0 + fn * 8 + c2) = make_float2(o[fn][0] * inv0, o[fn][1] * inv0);
        *(float2*)(ob1 + fn * 8 + c2) = make_float2(o[fn][2] * inv1, o[fn][3] * inv1);
    }
}

// ---------------- launch ----------------
static void* sym_addr(const void* symbol) {
    void* p = nullptr;
    cudaGetSymbolAddress(&p, symbol);
    return p;
}

extern "C" void kernel_launch(void* const* d_in, const int* in_sizes, int n_in,
                              void* d_out, int out_size)
{
    const float* x    = (const float*)d_in[0];
    const float* cosp = (const float*)d_in[1];
    const float* sinp = (const float*)d_in[2];
    const float* Wq   = (const float*)d_in[3];
    const float* qw   = (const float*)d_in[4];
    const float* Wkva = (const float*)d_in[5];
    const float* kvaw = (const float*)d_in[6];
    const float* Wkvb = (const float*)d_in[7];
    const float* Wo   = (const float*)d_in[8];
    float* out = (float*)d_out;

    float* qraw = (float*)sym_addr(g_qraw);
    float* kva  = (float*)sym_addr(g_kva);
    float* lat  = (float*)sym_addr(g_lat);
    float* kvb  = (float*)sym_addr(g_kvb);
    float* ao   = (float*)sym_addr(g_ao);

    __half* xh  = (__half*)sym_addr(g_xh);
    __half* wqh = (__half*)sym_addr(g_Wqh); __half* wql = (__half*)sym_addr(g_Wql);
    __half* wah = (__half*)sym_addr(g_Wah); __half* wal = (__half*)sym_addr(g_Wal);
    __half* wbh = (__half*)sym_addr(g_Wbh); __half* wbl = (__half*)sym_addr(g_Wbl);
    __half* woh = (__half*)sym_addr(g_Woh); __half* wol = (__half*)sym_addr(g_Wol);
    __half* lth = (__half*)sym_addr(g_lth);
    __half* aoh = (__half*)sym_addr(g_aoh);

    cudaFuncSetAttribute(gemm2t, cudaFuncAttributeMaxDynamicSharedMemorySize, 2 * GBUF_B);

    auto cvt1 = [&](const float* s, __half* d, int npad, int nreal) {
        int blocks = (npad / 4 + 255) / 256; if (blocks > 8192) blocks = 8192;
        cvt_h<<<blocks, 256>>>(s, d, npad, nreal);
    };
    auto cvt2 = [&](const float* s, __half* dh, __half* dl, int npad, int nreal) {
        int blocks = (npad / 4 + 255) / 256; if (blocks > 8192) blocks = 8192;
        cvt_hl<<<blocks, 256>>>(s, dh, dl, npad, nreal);
    };

    // 0) conversions
    cvt1(x,    xh,  MTOT * DD, MTOT * DD);
    cvt2(Wq,   wqh, wql, DD * DD, DD * DD);
    cvt2(Wkva, wah, wal, KVA_PAD * DD, KVA_N * DD);
    cvt2(Wkvb, wbh, wbl, KVB_N * RR, KVB_N * RR);
    cvt2(Wo,   woh, wol, DD * DD, DD * DD);

    // 1) q projection + kv_a projection
    {
        dim3 g(DD / 128, MTOT / 128);
        gemm2t<<<g, 256, 2 * GBUF_B>>>(xh, wqh, wql, qraw, DD, NH * HD, NH * HD);
    }
    {
        dim3 g(KVA_PAD / 128, MTOT / 128);
        gemm2t<<<g, 256, 2 * GBUF_B>>>(xh, wah, wal, kva, DD, KVA_N, KVA_N);
    }

    // 2) norms + rope
    q_post_kernel<<<MTOT * NH, 64>>>(cosp, sinp, qw);
    kva_post_kernel<<<MTOT, 128>>>(cosp, sinp, kvaw);

    // 3) kv_b projection + assemble
    cvt1(lat, lth, MTOT * RR, MTOT * RR);
    {
        dim3 g(KVB_N / 128, MTOT / 128);
        gemm2t<<<g, 256, 2 * GBUF_B>>>(lth, wbh, wbl, kvb, RR, KVB_N, KVB_N);
    }
    assemble_kernel<<<4096, 256>>>();

    // 4) flash attention
    {
        dim3 g(TT / 128, BB * NH);
        flash_mma<<<g, 256>>>();
    }

    // 5) output projection
    cvt1(ao, aoh, MTOT * DD, MTOT * DD);
    {
        dim3 g(DD / 128, MTOT / 128);
        gemm2t<<<g, 256, 2 * GBUF_B>>>(aoh, woh, wol, out, DD, DD, DD);
    }
}

// round 6
// speedup vs baseline: 3.8455x; 1.0846x over previous
#include <cuda_runtime.h>
#include <cuda_fp16.h>
#include <math.h>
#include <cstdint>

#define BB 2
#define TT 2048
#define DD 1024
#define NH 16
#define HD 64      // NOPE_D + ROPE_D
#define NOPE 48
#define ROPED 16
#define RR 128
#define VD 64
#define KVB_N (NH * (NOPE + VD))   // 1792
#define KVA_N (RR + ROPED)         // 144
#define KVA_PAD 256
#define MTOT (BB * TT)             // 4096

// ---------------- scratch ----------------
__device__ float g_qraw[MTOT * NH * HD];
__device__ float g_kva [MTOT * KVA_N];
__device__ float g_lat [MTOT * RR];
__device__ float g_krope[MTOT * ROPED];
__device__ float g_kvb [MTOT * KVB_N];

// attention operands fp16, layout [b*NH+h][t][64]
__device__ __align__(256) __half g_qh[BB*NH*TT*HD], g_ql[BB*NH*TT*HD];
__device__ __align__(256) __half g_kh[BB*NH*TT*HD], g_kl[BB*NH*TT*HD];
__device__ __align__(256) __half g_vh[BB*NH*TT*VD];

// fp16 GEMM operands
__device__ __align__(256) __half g_xh [MTOT * DD];
__device__ __align__(256) __half g_Wqh[DD * DD],      g_Wql[DD * DD];
__device__ __align__(256) __half g_Wah[KVA_PAD * DD], g_Wal[KVA_PAD * DD];
__device__ __align__(256) __half g_Wbh[KVB_N * RR],   g_Wbl[KVB_N * RR];
__device__ __align__(256) __half g_Woh[DD * DD],      g_Wol[DD * DD];
__device__ __align__(256) __half g_lth[MTOT * RR];
__device__ __align__(256) __half g_aoh[MTOT * DD];    // flash output, fp16

// ======================= helpers =======================
__device__ __forceinline__ uint32_t smem_u32(const void* p) {
    uint32_t a;
    asm("{ .reg .u64 t; cvta.to.shared.u64 t, %1; cvt.u32.u64 %0, t; }" : "=r"(a) : "l"(p));
    return a;
}
__device__ __forceinline__ void mma16816(float* c, const uint32_t* a, const uint32_t* b) {
    asm volatile("mma.sync.aligned.m16n8k16.row.col.f32.f16.f16.f32 "
        "{%0,%1,%2,%3}, {%4,%5,%6,%7}, {%8,%9}, {%0,%1,%2,%3};"
        : "+f"(c[0]), "+f"(c[1]), "+f"(c[2]), "+f"(c[3])
        : "r"(a[0]), "r"(a[1]), "r"(a[2]), "r"(a[3]), "r"(b[0]), "r"(b[1]));
}
__device__ __forceinline__ void ldsm4(uint32_t* r, uint32_t addr) {
    asm volatile("ldmatrix.sync.aligned.m8n8.x4.shared.b16 {%0,%1,%2,%3}, [%4];"
        : "=r"(r[0]), "=r"(r[1]), "=r"(r[2]), "=r"(r[3]) : "r"(addr));
}
__device__ __forceinline__ void ldsm4t(uint32_t* r, uint32_t addr) {
    asm volatile("ldmatrix.sync.aligned.m8n8.x4.trans.shared.b16 {%0,%1,%2,%3}, [%4];"
        : "=r"(r[0]), "=r"(r[1]), "=r"(r[2]), "=r"(r[3]) : "r"(addr));
}
__device__ __forceinline__ uint32_t packh(float lo, float hi) {
    uint32_t d;
    asm("cvt.rn.f16x2.f32 %0, %1, %2;" : "=r"(d) : "f"(hi), "f"(lo));
    return d;
}

// ======================= fused conversions =======================
// segment quads (4 elems each)
#define QX  (MTOT * DD / 4)          // 1048576
#define QWQ (DD * DD / 4)            // 262144
#define QWA (KVA_PAD * DD / 4)       // 65536
#define QWB (KVB_N * RR / 4)         // 57344
#define QWO (DD * DD / 4)            // 262144
#define QTOT (QX + QWQ + QWA + QWB + QWO)

__device__ __forceinline__ void do_hl(const float* s, __half* dh, __half* dl, int e) {
    float4 v = *(const float4*)(s + e);
    __half h0 = __float2half(v.x), h1 = __float2half(v.y);
    __half h2 = __float2half(v.z), h3 = __float2half(v.w);
    ((__half2*)(dh + e))[0] = __half2(h0, h1);
    ((__half2*)(dh + e))[1] = __half2(h2, h3);
    __half l0 = __float2half(v.x - __half2float(h0));
    __half l1 = __float2half(v.y - __half2float(h1));
    __half l2 = __float2half(v.z - __half2float(h2));
    __half l3 = __float2half(v.w - __half2float(h3));
    ((__half2*)(dl + e))[0] = __half2(l0, l1);
    ((__half2*)(dl + e))[1] = __half2(l2, l3);
}

__global__ __launch_bounds__(256) void cvt_all(
    const float* __restrict__ x,    const float* __restrict__ Wq,
    const float* __restrict__ Wkva, const float* __restrict__ Wkvb,
    const float* __restrict__ Wo)
{
    int qi = blockIdx.x * blockDim.x + threadIdx.x;
    if (qi >= QTOT) return;
    if (qi < QX) {
        int e = qi * 4;
        float4 v = *(const float4*)(x + e);
        ((__half2*)(g_xh + e))[0] = __half2(__float2half(v.x), __float2half(v.y));
        ((__half2*)(g_xh + e))[1] = __half2(__float2half(v.z), __float2half(v.w));
        return;
    }
    qi -= QX;
    if (qi < QWQ) { do_hl(Wq, g_Wqh, g_Wql, qi * 4); return; }
    qi -= QWQ;
    if (qi < QWA) {
        int e = qi * 4;
        if (e < KVA_N * DD) do_hl(Wkva, g_Wah, g_Wal, e);
        else {
            ((__half2*)(g_Wah + e))[0] = __half2(__half(0.f), __half(0.f));
            ((__half2*)(g_Wah + e))[1] = __half2(__half(0.f), __half(0.f));
            ((__half2*)(g_Wal + e))[0] = __half2(__half(0.f), __half(0.f));
            ((__half2*)(g_Wal + e))[1] = __half2(__half(0.f), __half(0.f));
        }
        return;
    }
    qi -= QWA;
    if (qi < QWB) { do_hl(Wkvb, g_Wbh, g_Wbl, qi * 4); return; }
    qi -= QWB;
    do_hl(Wo, g_Woh, g_Wol, qi * 4);
}

__global__ __launch_bounds__(256) void cvt_h(
    const float* __restrict__ s, __half* __restrict__ d, int n)
{
    int e = (blockIdx.x * blockDim.x + threadIdx.x) * 4;
    if (e >= n) return;
    float4 v = *(const float4*)(s + e);
    ((__half2*)(d + e))[0] = __half2(__float2half(v.x), __float2half(v.y));
    ((__half2*)(d + e))[1] = __half2(__float2half(v.z), __float2half(v.w));
}

// ======================= 2-term fp16 GEMM, 3-stage pipeline =======================
#define GPAD 40
#define GTILE_B (128 * GPAD * 2)     // 10240
#define GBUF_B  (3 * GTILE_B)        // 30720 (A, Bh, Bl)
#define NSTAGE 3

__global__ __launch_bounds__(256, 2) void gemm2t(
    const __half* __restrict__ Ah, const __half* __restrict__ Bh,
    const __half* __restrict__ Bl, float* __restrict__ C,
    int K, int Nreal, int ldc)
{
    extern __shared__ __align__(16) char smem[];   // NSTAGE * GBUF_B = 92160

    const int tid = threadIdx.x, wid = tid >> 5, lane = tid & 31;
    const int warp_m = wid >> 2, warp_n = wid & 3;
    const int m0 = blockIdx.y * 128, n0 = blockIdx.x * 128;
    uint32_t smem_base = smem_u32(smem);

    const char* base[3] = { (const char*)(Ah + (size_t)m0 * K),
                            (const char*)(Bh + (size_t)n0 * K),
                            (const char*)(Bl + (size_t)n0 * K) };
    const size_t ldbytes = (size_t)K * 2;
    const int nch = K >> 5;

    float acc[4][4][4];
    #pragma unroll
    for (int i = 0; i < 4; i++)
        #pragma unroll
        for (int j = 0; j < 4; j++)
            #pragma unroll
            for (int e = 0; e < 4; e++) acc[i][j][e] = 0.f;

    auto load_chunk = [&](int ch, int buf) {
        const int k0b = (ch << 5) * 2;
        #pragma unroll
        for (int it = 0; it < 6; it++) {
            int i = tid + it * 256;
            int mat = i >> 9, rem = i & 511;
            int row = rem >> 2, seg = rem & 3;
            const char* src = base[mat] + (size_t)row * ldbytes + k0b + seg * 16;
            uint32_t dst = smem_base + buf * GBUF_B + mat * GTILE_B
                         + (row * GPAD + seg * 8) * 2;
            asm volatile("cp.async.cg.shared.global [%0], [%1], 16;" :: "r"(dst), "l"(src));
        }
        asm volatile("cp.async.commit_group;");
    };

    auto compute_chunk = [&](int buf) {
        const uint32_t smA  = smem_base + buf * GBUF_B;
        const uint32_t smBh = smA + GTILE_B;
        const uint32_t smBl = smBh + GTILE_B;
        const int lm = lane & 15, lh = lane >> 4;
        const int g = lane >> 3, r = lane & 7;
        #pragma unroll
        for (int k16 = 0; k16 < 2; k16++) {
            uint32_t a[4][4];
            #pragma unroll
            for (int fm = 0; fm < 4; fm++) {
                uint32_t addr = smA + ((warp_m * 64 + fm * 16 + lm) * GPAD
                                       + k16 * 16 + lh * 8) * 2;
                ldsm4(a[fm], addr);
            }
            uint32_t bh[4][2], bl[4][2];
            #pragma unroll
            for (int fp = 0; fp < 2; fp++) {
                int row = warp_n * 32 + fp * 16 + ((g >> 1) << 3) + r;
                int off = (row * GPAD + (g & 1) * 8 + k16 * 16) * 2;
                uint32_t t4[4];
                ldsm4(t4, smBh + off);
                bh[fp*2][0]=t4[0]; bh[fp*2][1]=t4[1]; bh[fp*2+1][0]=t4[2]; bh[fp*2+1][1]=t4[3];
                ldsm4(t4, smBl + off);
                bl[fp*2][0]=t4[0]; bl[fp*2][1]=t4[1]; bl[fp*2+1][0]=t4[2]; bl[fp*2+1][1]=t4[3];
            }
            #pragma unroll
            for (int fm = 0; fm < 4; fm++)
                #pragma unroll
                for (int fn = 0; fn < 4; fn++) {
                    mma16816(acc[fm][fn], a[fm], bh[fn]);
                    mma16816(acc[fm][fn], a[fm], bl[fn]);
                }
        }
    };

    // prologue: 2 chunks in flight
    load_chunk(0, 0);
    if (nch > 1) load_chunk(1, 1);
    else asm volatile("cp.async.commit_group;");

    for (int ch = 0; ch < nch; ch++) {
        asm volatile("cp.async.wait_group 1;");   // chunk ch arrived
        __syncthreads();                           // all warps done with buf (ch-1)%3
        if (ch + 2 < nch) load_chunk(ch + 2, (ch + 2) % NSTAGE);
        else asm volatile("cp.async.commit_group;");
        compute_chunk(ch % NSTAGE);
    }

    const int r4 = lane >> 2, c2 = (lane & 3) * 2;
    #pragma unroll
    for (int fm = 0; fm < 4; fm++) {
        #pragma unroll
        for (int fn = 0; fn < 4; fn++) {
            int m = m0 + warp_m * 64 + fm * 16 + r4;
            int n = n0 + warp_n * 32 + fn * 8 + c2;
            if (n < Nreal) {
                *(float2*)&C[(size_t)m * ldc + n] =
                    make_float2(acc[fm][fn][0], acc[fm][fn][1]);
                *(float2*)&C[(size_t)(m + 8) * ldc + n] =
                    make_float2(acc[fm][fn][2], acc[fm][fn][3]);
            }
        }
    }
}

// ---------------- q post: warp per (bt,h) row ----------------
__global__ __launch_bounds__(256) void q_post_kernel(
    const float* __restrict__ cosp, const float* __restrict__ sinp,
    const float* __restrict__ qw)
{
    int row = blockIdx.x * 8 + (threadIdx.x >> 5);   // (b*T + t)*NH + h
    int lane = threadIdx.x & 31;
    int h  = row & (NH - 1);
    int bt = row >> 4;
    int t  = bt & (TT - 1);
    int b  = bt >> 11;

    const float* src = g_qraw + (size_t)bt * (NH * HD) + h * HD;
    float v0 = src[lane], v1 = src[lane + 32];
    float ss = v0 * v0 + v1 * v1;
    #pragma unroll
    for (int o = 16; o; o >>= 1) ss += __shfl_xor_sync(~0u, ss, o);
    float norm = rsqrtf(ss * (1.0f / HD) + 1e-6f);
    v0 *= norm * qw[lane];
    v1 *= norm * qw[lane + 32];

    // RoPE on dims 48..63 (all live in v1, lanes 16..31)
    float pv = __shfl_xor_sync(~0u, v1, 8);
    int d1 = lane + 32;
    if (d1 >= NOPE) {
        int i = d1 & 7;
        float c = cosp[t * 8 + i], s = sinp[t * 8 + i];
        v1 = (d1 < NOPE + 8) ? (v1 * c - pv * s) : (v1 * c + pv * s);
    }
    size_t dst = (((size_t)(b * NH + h)) * TT + t) * HD;
    __half h0 = __float2half(v0), h1 = __float2half(v1);
    g_qh[dst + lane] = h0;
    g_qh[dst + lane + 32] = h1;
    g_ql[dst + lane] = __float2half(v0 - __half2float(h0));
    g_ql[dst + lane + 32] = __float2half(v1 - __half2float(h1));
}

// ---------------- kv_a post ----------------
__global__ __launch_bounds__(128) void kva_post_kernel(
    const float* __restrict__ cosp, const float* __restrict__ sinp,
    const float* __restrict__ kvaw)
{
    int bt = blockIdx.x;
    int t  = bt & (TT - 1);
    int tid = threadIdx.x;

    float v = g_kva[(size_t)bt * KVA_N + tid];
    float ss = v * v;
    #pragma unroll
    for (int o = 16; o; o >>= 1) ss += __shfl_xor_sync(~0u, ss, o);
    __shared__ float red[4];
    if ((tid & 31) == 0) red[tid >> 5] = ss;
    __syncthreads();
    float tot = red[0] + red[1] + red[2] + red[3];
    float norm = rsqrtf(tot * (1.0f / RR) + 1e-6f);
    g_lat[(size_t)bt * RR + tid] = v * norm * kvaw[tid];

    if (tid < 32) {
        float rv = (tid < ROPED) ? g_kva[(size_t)bt * KVA_N + RR + tid] : 0.f;
        float pv = __shfl_xor_sync(~0u, rv, 8);
        if (tid < ROPED) {
            int i = tid & 7;
            float c = cosp[t * 8 + i], s = sinp[t * 8 + i];
            float outv = (tid < 8) ? (rv * c - pv * s) : (rv * c + pv * s);
            g_krope[(size_t)bt * ROPED + tid] = outv;
        }
    }
}

// ---------------- assemble k (hi/lo) / v (hi) -> [bh][t][d] ----------------
__global__ __launch_bounds__(256) void assemble_kernel()
{
    const int NTOT = BB * NH * TT * HD;
    for (int idx = blockIdx.x * blockDim.x + threadIdx.x; idx < NTOT;
         idx += gridDim.x * blockDim.x) {
        int d = idx & 63;
        int t = (idx >> 6) & (TT - 1);
        int h = (idx >> 17) & (NH - 1);
        int b = idx >> 21;
        size_t bt = (size_t)b * TT + t;
        float kv;
        if (d < NOPE) kv = g_kvb[bt * KVB_N + h * (NOPE + VD) + d];
        else          kv = g_krope[bt * ROPED + (d - NOPE)];
        float vv = g_kvb[bt * KVB_N + h * (NOPE + VD) + NOPE + d];
        __half kh = __float2half(kv);
        g_kh[idx] = kh;
        g_kl[idx] = __float2half(kv - __half2float(kh));
        g_vh[idx] = __float2half(vv);
    }
}

// ---------------- flash attention (fp16: S 3-term, PV 2-term) ----------------
#define FPAD 72

__global__ __launch_bounds__(256) void flash_mma()
{
    __shared__ __align__(16) __half sm[2 * 128 * FPAD];   // 36864 B

    const int tid = threadIdx.x, wid = tid >> 5, lane = tid & 31;
    const int bh = blockIdx.y;
    const int b = bh >> 4, h = bh & (NH - 1);
    const int qtile = gridDim.x - 1 - blockIdx.x;
    const int qb = qtile * 128;
    const uint32_t sb = smem_u32(sm);

    const int lm = lane & 15, lh = lane >> 4;
    const int g = lane >> 3, r8 = lane & 7;
    const int r4 = lane >> 2, c2 = (lane & 3) * 2;

    // ---- stage Q (hi + lo) ----
    {
        const __half* qhp = g_qh + ((size_t)bh * TT + qb) * HD;
        const __half* qlp = g_ql + ((size_t)bh * TT + qb) * HD;
        for (int i = tid; i < 128 * 8; i += 256) {
            int r = i >> 3, s = i & 7;
            *(uint4*)(sm + r * FPAD + s * 8) = *(const uint4*)(qhp + r * 64 + s * 8);
            *(uint4*)(sm + 128 * FPAD + r * FPAD + s * 8) = *(const uint4*)(qlp + r * 64 + s * 8);
        }
    }
    __syncthreads();

    uint32_t qh[4][4], ql[4][4];
    #pragma unroll
    for (int ks = 0; ks < 4; ks++) {
        uint32_t addr = sb + ((wid * 16 + lm) * FPAD + ks * 16 + lh * 8) * 2;
        ldsm4(qh[ks], addr);
        ldsm4(ql[ks], addr + 128 * FPAD * 2);
    }

    float o[8][4];
    #pragma unroll
    for (int i = 0; i < 8; i++)
        #pragma unroll
        for (int e = 0; e < 4; e++) o[i][e] = 0.f;
    float mrow[2] = { -1e30f, -1e30f };
    float lsum[2] = { 0.f, 0.f };

    const __half* khb = g_kh + (size_t)bh * TT * HD;
    const __half* klb = g_kl + (size_t)bh * TT * HD;
    const __half* vhb = g_vh + (size_t)bh * TT * VD;

    const int ntiles = qtile * 2 + 2;
    const float scale = 0.125f;
    const int q0 = qb + wid * 16 + r4;
    const int q1 = q0 + 8;

    const uint32_t oKl = 64 * FPAD * 2;
    const uint32_t oVh = 2 * 64 * FPAD * 2;

    for (int it = 0; it < ntiles; it++) {
        const int j0 = it * 64;
        __syncthreads();
        for (int i = tid; i < 64 * 8; i += 256) {
            int r = i >> 3, s = i & 7;
            size_t gsrc = (size_t)(j0 + r) * 64 + s * 8;
            int dsh = r * FPAD + s * 8;
            *(uint4*)(sm + dsh) = *(const uint4*)(khb + gsrc);
            *(uint4*)(sm + 64 * FPAD + dsh) = *(const uint4*)(klb + gsrc);
            *(uint4*)(sm + 2 * 64 * FPAD + dsh) = *(const uint4*)(vhb + gsrc);
        }
        __syncthreads();

        float s[8][4];
        #pragma unroll
        for (int i = 0; i < 8; i++)
            #pragma unroll
            for (int e = 0; e < 4; e++) s[i][e] = 0.f;

        #pragma unroll
        for (int fp = 0; fp < 4; fp++) {
            const int krow = fp * 16 + ((g >> 1) << 3) + r8;
            const int kcol = (g & 1) * 8;
            #pragma unroll
            for (int ks = 0; ks < 4; ks++) {
                uint32_t addr = sb + (krow * FPAD + kcol + ks * 16) * 2;
                uint32_t bhf[4], blf[4];
                ldsm4(bhf, addr);
                ldsm4(blf, addr + oKl);
                uint32_t bh0[2] = { bhf[0], bhf[1] }, bh1[2] = { bhf[2], bhf[3] };
                uint32_t bl0[2] = { blf[0], blf[1] }, bl1[2] = { blf[2], blf[3] };
                mma16816(s[fp*2],   qh[ks], bh0);
                mma16816(s[fp*2],   qh[ks], bl0);
                mma16816(s[fp*2],   ql[ks], bh0);
                mma16816(s[fp*2+1], qh[ks], bh1);
                mma16816(s[fp*2+1], qh[ks], bl1);
                mma16816(s[fp*2+1], ql[ks], bh1);
            }
        }

        const bool need_mask = (it >= ntiles - 2);
        #pragma unroll
        for (int fn = 0; fn < 8; fn++) {
            #pragma unroll
            for (int e = 0; e < 4; e++) {
                float x = s[fn][e] * scale;
                if (need_mask) {
                    int kv = j0 + fn * 8 + c2 + (e & 1);
                    int qq = (e < 2) ? q0 : q1;
                    if (kv > qq) x = -1e30f;
                }
                s[fn][e] = x;
            }
        }

        float tm0 = -1e30f, tm1 = -1e30f;
        #pragma unroll
        for (int fn = 0; fn < 8; fn++) {
            tm0 = fmaxf(tm0, fmaxf(s[fn][0], s[fn][1]));
            tm1 = fmaxf(tm1, fmaxf(s[fn][2], s[fn][3]));
        }
        tm0 = fmaxf(tm0, __shfl_xor_sync(~0u, tm0, 1));
        tm0 = fmaxf(tm0, __shfl_xor_sync(~0u, tm0, 2));
        tm1 = fmaxf(tm1, __shfl_xor_sync(~0u, tm1, 1));
        tm1 = fmaxf(tm1, __shfl_xor_sync(~0u, tm1, 2));

        float mn0 = fmaxf(mrow[0], tm0), mn1 = fmaxf(mrow[1], tm1);
        float cr0 = __expf(mrow[0] - mn0), cr1 = __expf(mrow[1] - mn1);
        mrow[0] = mn0; mrow[1] = mn1;
        lsum[0] *= cr0; lsum[1] *= cr1;
        #pragma unroll
        for (int fn = 0; fn < 8; fn++) {
            o[fn][0] *= cr0; o[fn][1] *= cr0;
            o[fn][2] *= cr1; o[fn][3] *= cr1;
        }

        #pragma unroll
        for (int fn = 0; fn < 8; fn++) {
            s[fn][0] = __expf(s[fn][0] - mn0);
            s[fn][1] = __expf(s[fn][1] - mn0);
            s[fn][2] = __expf(s[fn][2] - mn1);
            s[fn][3] = __expf(s[fn][3] - mn1);
            lsum[0] += s[fn][0] + s[fn][1];
            lsum[1] += s[fn][2] + s[fn][3];
        }

        #pragma unroll
        for (int ks = 0; ks < 4; ks++) {
            float p0[4] = { s[ks*2][0], s[ks*2][1], s[ks*2][2], s[ks*2][3] };
            float p1[4] = { s[ks*2+1][0], s[ks*2+1][1], s[ks*2+1][2], s[ks*2+1][3] };
            uint32_t aph[4], apl[4];
            aph[0] = packh(p0[0], p0[1]); aph[1] = packh(p0[2], p0[3]);
            aph[2] = packh(p1[0], p1[1]); aph[3] = packh(p1[2], p1[3]);
            float h0[4], h1[4];
            #pragma unroll
            for (int e = 0; e < 4; e++) {
                h0[e] = __half2float(__float2half(p0[e]));
                h1[e] = __half2float(__float2half(p1[e]));
            }
            apl[0] = packh(p0[0]-h0[0], p0[1]-h0[1]);
            apl[1] = packh(p0[2]-h0[2], p0[3]-h0[3]);
            apl[2] = packh(p1[0]-h1[0], p1[1]-h1[1]);
            apl[3] = packh(p1[2]-h1[2], p1[3]-h1[3]);

            const int vrow = ks * 16 + (g & 1) * 8 + r8;
            #pragma unroll
            for (int np = 0; np < 4; np++) {
                const int vcol = np * 16 + lh * 8;
                uint32_t addr = sb + oVh + (vrow * FPAD + vcol) * 2;
                uint32_t bvh[4];
                ldsm4t(bvh, addr);
                uint32_t b0[2] = { bvh[0], bvh[1] }, b1[2] = { bvh[2], bvh[3] };
                mma16816(o[np*2],   aph, b0);
                mma16816(o[np*2],   apl, b0);
                mma16816(o[np*2+1], aph, b1);
                mma16816(o[np*2+1], apl, b1);
            }
        }
    }

    lsum[0] += __shfl_xor_sync(~0u, lsum[0], 1);
    lsum[0] += __shfl_xor_sync(~0u, lsum[0], 2);
    lsum[1] += __shfl_xor_sync(~0u, lsum[1], 1);
    lsum[1] += __shfl_xor_sync(~0u, lsum[1], 2);
    const float inv0 = 1.f / lsum[0], inv1 = 1.f / lsum[1];

    // fp16 packed output directly into Wo's A operand
    __half* ob0 = g_aoh + ((size_t)(b * TT + q0)) * (NH * VD) + h * VD;
    __half* ob1 = g_aoh + ((size_t)(b * TT + q1)) * (NH * VD) + h * VD;
    #pragma unroll
    for (int fn = 0; fn < 8; fn++) {
        *(uint32_t*)(ob0 + fn * 8 + c2) = packh(o[fn][0] * inv0, o[fn][1] * inv0);
        *(uint32_t*)(ob1 + fn * 8 + c2) = packh(o[fn][2] * inv1, o[fn][3] * inv1);
    }
}

// ---------------- launch ----------------
static void* sym_addr(const void* symbol) {
    void* p = nullptr;
    cudaGetSymbolAddress(&p, symbol);
    return p;
}

extern "C" void kernel_launch(void* const* d_in, const int* in_sizes, int n_in,
                              void* d_out, int out_size)
{
    const float* x    = (const float*)d_in[0];
    const float* cosp = (const float*)d_in[1];
    const float* sinp = (const float*)d_in[2];
    const float* Wq   = (const float*)d_in[3];
    const float* qw   = (const float*)d_in[4];
    const float* Wkva = (const float*)d_in[5];
    const float* kvaw = (const float*)d_in[6];
    const float* Wkvb = (const float*)d_in[7];
    const float* Wo   = (const float*)d_in[8];
    float* out = (float*)d_out;

    float* qraw = (float*)sym_addr(g_qraw);
    float* kva  = (float*)sym_addr(g_kva);
    float* lat  = (float*)sym_addr(g_lat);
    float* kvb  = (float*)sym_addr(g_kvb);

    __half* xh  = (__half*)sym_addr(g_xh);
    __half* wqh = (__half*)sym_addr(g_Wqh); __half* wql = (__half*)sym_addr(g_Wql);
    __half* wah = (__half*)sym_addr(g_Wah); __half* wal = (__half*)sym_addr(g_Wal);
    __half* wbh = (__half*)sym_addr(g_Wbh); __half* wbl = (__half*)sym_addr(g_Wbl);
    __half* woh = (__half*)sym_addr(g_Woh); __half* wol = (__half*)sym_addr(g_Wol);
    __half* lth = (__half*)sym_addr(g_lth);
    __half* aoh = (__half*)sym_addr(g_aoh);

    cudaFuncSetAttribute(gemm2t, cudaFuncAttributeMaxDynamicSharedMemorySize,
                         NSTAGE * GBUF_B);

    // 0) fused conversions
    cvt_all<<<(QTOT + 255) / 256, 256>>>(x, Wq, Wkva, Wkvb, Wo);

    // 1) q projection + kv_a projection
    {
        dim3 g(DD / 128, MTOT / 128);
        gemm2t<<<g, 256, NSTAGE * GBUF_B>>>(xh, wqh, wql, qraw, DD, NH * HD, NH * HD);
    }
    {
        dim3 g(KVA_PAD / 128, MTOT / 128);
        gemm2t<<<g, 256, NSTAGE * GBUF_B>>>(xh, wah, wal, kva, DD, KVA_N, KVA_N);
    }

    // 2) norms + rope
    q_post_kernel<<<MTOT * NH / 8, 256>>>(cosp, sinp, qw);
    kva_post_kernel<<<MTOT, 128>>>(cosp, sinp, kvaw);

    // 3) kv_b projection + assemble
    cvt_h<<<(MTOT * RR / 4 + 255) / 256, 256>>>(lat, lth, MTOT * RR);
    {
        dim3 g(KVB_N / 128, MTOT / 128);
        gemm2t<<<g, 256, NSTAGE * GBUF_B>>>(lth, wbh, wbl, kvb, RR, KVB_N, KVB_N);
    }
    assemble_kernel<<<4096, 256>>>();

    // 4) flash attention -> fp16 aoh
    {
        dim3 g(TT / 128, BB * NH);
        flash_mma<<<g, 256>>>();
    }

    // 5) output projection
    {
        dim3 g(DD / 128, MTOT / 128);
        gemm2t<<<g, 256, NSTAGE * GBUF_B>>>(aoh, woh, wol, out, DD, DD, DD);
    }
}

// round 7
// speedup vs baseline: 3.8645x; 1.0049x over previous
#include <cuda_runtime.h>
#include <cuda_fp16.h>
#include <math.h>
#include <cstdint>

#define BB 2
#define TT 2048
#define DD 1024
#define NH 16
#define HD 64      // NOPE_D + ROPE_D
#define NOPE 48
#define ROPED 16
#define RR 128
#define VD 64
#define KVB_N (NH * (NOPE + VD))   // 1792
#define MTOT (BB * TT)             // 4096
#define W1_ROWS 1280               // 1024 (Wq) + 128 (latent) + 16 (rope) + 112 pad

// ---------------- device scratch ----------------
// attention operands fp16, layout [b*NH+h][t][64]
__device__ __align__(256) __half g_qh[BB*NH*TT*HD], g_ql[BB*NH*TT*HD];
__device__ __align__(256) __half g_kh[BB*NH*TT*HD], g_kl[BB*NH*TT*HD];
__device__ __align__(256) __half g_vh[BB*NH*TT*VD];

// fp16 GEMM operands
__device__ __align__(256) __half g_xh [MTOT * DD];
__device__ __align__(256) __half g_W1h[W1_ROWS * DD], g_W1l[W1_ROWS * DD];
__device__ __align__(256) __half g_Wbh[KVB_N * RR],   g_Wbl[KVB_N * RR];
__device__ __align__(256) __half g_Woh[DD * DD],      g_Wol[DD * DD];
__device__ __align__(256) __half g_lth[MTOT * RR];    // rms(latent), fp16 hi
__device__ __align__(256) __half g_aoh[MTOT * DD];    // flash output fp16

// ======================= helpers =======================
__device__ __forceinline__ uint32_t smem_u32(const void* p) {
    uint32_t a;
    asm("{ .reg .u64 t; cvta.to.shared.u64 t, %1; cvt.u32.u64 %0, t; }" : "=r"(a) : "l"(p));
    return a;
}
__device__ __forceinline__ void mma16816(float* c, const uint32_t* a, const uint32_t* b) {
    asm volatile("mma.sync.aligned.m16n8k16.row.col.f32.f16.f16.f32 "
        "{%0,%1,%2,%3}, {%4,%5,%6,%7}, {%8,%9}, {%0,%1,%2,%3};"
        : "+f"(c[0]), "+f"(c[1]), "+f"(c[2]), "+f"(c[3])
        : "r"(a[0]), "r"(a[1]), "r"(a[2]), "r"(a[3]), "r"(b[0]), "r"(b[1]));
}
__device__ __forceinline__ void ldsm4(uint32_t* r, uint32_t addr) {
    asm volatile("ldmatrix.sync.aligned.m8n8.x4.shared.b16 {%0,%1,%2,%3}, [%4];"
        : "=r"(r[0]), "=r"(r[1]), "=r"(r[2]), "=r"(r[3]) : "r"(addr));
}
__device__ __forceinline__ void ldsm4t(uint32_t* r, uint32_t addr) {
    asm volatile("ldmatrix.sync.aligned.m8n8.x4.trans.shared.b16 {%0,%1,%2,%3}, [%4];"
        : "=r"(r[0]), "=r"(r[1]), "=r"(r[2]), "=r"(r[3]) : "r"(addr));
}
__device__ __forceinline__ uint32_t packh(float lo, float hi) {
    uint32_t d;
    asm("cvt.rn.f16x2.f32 %0, %1, %2;" : "=r"(d) : "f"(hi), "f"(lo));
    return d;
}
__device__ __forceinline__ uint32_t pack_lo_resid(float v0, float v1) {
    float h0 = __half2float(__float2half(v0));
    float h1 = __half2float(__float2half(v1));
    return packh(v0 - h0, v1 - h1);
}

// ======================= fused conversions =======================
#define QX  (MTOT * DD / 4)
#define QW1 (W1_ROWS * DD / 4)
#define QWB (KVB_N * RR / 4)
#define QWO (DD * DD / 4)
#define QTOT (QX + QW1 + QWB + QWO)

__device__ __forceinline__ void do_hl(const float* s, __half* dh, __half* dl, int e) {
    float4 v = *(const float4*)(s + e);
    __half h0 = __float2half(v.x), h1 = __float2half(v.y);
    __half h2 = __float2half(v.z), h3 = __float2half(v.w);
    ((__half2*)(dh + e))[0] = __half2(h0, h1);
    ((__half2*)(dh + e))[1] = __half2(h2, h3);
    ((__half2*)(dl + e))[0] = __half2(__float2half(v.x - __half2float(h0)),
                                      __float2half(v.y - __half2float(h1)));
    ((__half2*)(dl + e))[1] = __half2(__float2half(v.z - __half2float(h2)),
                                      __float2half(v.w - __half2float(h3)));
}

__global__ __launch_bounds__(256) void cvt_all(
    const float* __restrict__ x,    const float* __restrict__ Wq,
    const float* __restrict__ Wkva, const float* __restrict__ Wkvb,
    const float* __restrict__ Wo)
{
    int qi = blockIdx.x * blockDim.x + threadIdx.x;
    if (qi >= QTOT) return;
    if (qi < QX) {
        int e = qi * 4;
        float4 v = *(const float4*)(x + e);
        ((__half2*)(g_xh + e))[0] = __half2(__float2half(v.x), __float2half(v.y));
        ((__half2*)(g_xh + e))[1] = __half2(__float2half(v.z), __float2half(v.w));
        return;
    }
    qi -= QX;
    if (qi < QW1) {
        int e = qi * 4;
        if (e < DD * DD) { do_hl(Wq, g_W1h, g_W1l, e); /*src offset == dst*/ }
        else if (e < (DD + 144) * DD) {
            // Wkva rows: W1 row 1024+w <- Wkva row w ; contiguous elements
            float4 v = *(const float4*)(Wkva + (e - DD * DD));
            __half h0 = __float2half(v.x), h1 = __float2half(v.y);
            __half h2 = __float2half(v.z), h3 = __float2half(v.w);
            ((__half2*)(g_W1h + e))[0] = __half2(h0, h1);
            ((__half2*)(g_W1h + e))[1] = __half2(h2, h3);
            ((__half2*)(g_W1l + e))[0] = __half2(__float2half(v.x - __half2float(h0)),
                                                 __float2half(v.y - __half2float(h1)));
            ((__half2*)(g_W1l + e))[1] = __half2(__float2half(v.z - __half2float(h2)),
                                                 __float2half(v.w - __half2float(h3)));
        } else {
            __half2 z(__half(0.f), __half(0.f));
            ((__half2*)(g_W1h + e))[0] = z; ((__half2*)(g_W1h + e))[1] = z;
            ((__half2*)(g_W1l + e))[0] = z; ((__half2*)(g_W1l + e))[1] = z;
        }
        return;
    }
    qi -= QW1;
    if (qi < QWB) { do_hl(Wkvb, g_Wbh, g_Wbl, qi * 4); return; }
    qi -= QWB;
    do_hl(Wo, g_Woh, g_Wol, qi * 4);
}

// ======================= shared GEMM plumbing =======================
#define GPAD 40
#define GTILE_B (128 * GPAD * 2)     // 10240
#define GBUF_B  (3 * GTILE_B)        // 30720 (A, Bh, Bl)
#define NSTAGE 3

#define GEMM_LOAD_CHUNK(ch, buf)                                               \
    do {                                                                       \
        const int k0b = ((ch) << 5) * 2;                                       \
        _Pragma("unroll")                                                      \
        for (int it = 0; it < 6; it++) {                                       \
            int i = tid + it * 256;                                            \
            int mat = i >> 9, rem = i & 511;                                   \
            int row = rem >> 2, seg = rem & 3;                                 \
            const char* src = base[mat] + (size_t)row * ldbytes + k0b + seg * 16; \
            uint32_t dst = smem_base + (buf) * GBUF_B + mat * GTILE_B          \
                         + (row * GPAD + seg * 8) * 2;                         \
            asm volatile("cp.async.cg.shared.global [%0], [%1], 16;" :: "r"(dst), "l"(src)); \
        }                                                                      \
        asm volatile("cp.async.commit_group;");                                \
    } while (0)

// ======================= proj1: x @ [Wq|Wkva]^T with fused norm/rope epilogue
// warp tile m16 x n128 (8 warps), CTA 128x128, BK=32, 3-stage.
__global__ __launch_bounds__(256, 2) void proj1_gemm(
    const float* __restrict__ cosp, const float* __restrict__ sinp,
    const float* __restrict__ qw,   const float* __restrict__ kvaw)
{
    extern __shared__ __align__(16) char smem[];
    const int tid = threadIdx.x, wid = tid >> 5, lane = tid & 31;
    const int m0 = blockIdx.y * 128, n0 = blockIdx.x * 128;
    uint32_t smem_base = smem_u32(smem);

    const char* base[3] = { (const char*)(g_xh  + (size_t)m0 * DD),
                            (const char*)(g_W1h + (size_t)n0 * DD),
                            (const char*)(g_W1l + (size_t)n0 * DD) };
    const size_t ldbytes = (size_t)DD * 2;
    const int nch = DD >> 5;                      // 32

    const int lm = lane & 15, lh = lane >> 4;
    const int g = lane >> 3, r8 = lane & 7;
    const int r4 = lane >> 2, c2 = (lane & 3) * 2;

    float acc[16][4];
    #pragma unroll
    for (int i = 0; i < 16; i++)
        #pragma unroll
        for (int e = 0; e < 4; e++) acc[i][e] = 0.f;

    GEMM_LOAD_CHUNK(0, 0);
    GEMM_LOAD_CHUNK(1, 1);

    for (int ch = 0; ch < nch; ch++) {
        asm volatile("cp.async.wait_group 1;");
        __syncthreads();
        if (ch + 2 < nch) { GEMM_LOAD_CHUNK(ch + 2, (ch + 2) % NSTAGE); }
        else asm volatile("cp.async.commit_group;");
        const uint32_t smA  = smem_base + (ch % NSTAGE) * GBUF_B;
        const uint32_t smBh = smA + GTILE_B;
        const uint32_t smBl = smBh + GTILE_B;
        #pragma unroll
        for (int k16 = 0; k16 < 2; k16++) {
            uint32_t a[4];
            ldsm4(a, smA + ((wid * 16 + lm) * GPAD + k16 * 16 + lh * 8) * 2);
            #pragma unroll
            for (int fp = 0; fp < 8; fp++) {
                int row = fp * 16 + ((g >> 1) << 3) + r8;
                int off = (row * GPAD + (g & 1) * 8 + k16 * 16) * 2;
                uint32_t t4[4];
                ldsm4(t4, smBh + off);
                mma16816(acc[fp*2],   a, t4);
                mma16816(acc[fp*2+1], a, t4 + 2);
                ldsm4(t4, smBl + off);
                mma16816(acc[fp*2],   a, t4);
                mma16816(acc[fp*2+1], a, t4 + 2);
            }
        }
    }

    // ---------------- fused epilogue ----------------
    const int bt0 = m0 + wid * 16 + r4;      // row for acc[.][0..1]
    const int bt1 = bt0 + 8;                 // row for acc[.][2..3]
    const int t0 = bt0 & (TT - 1), t1 = bt1 & (TT - 1);
    const int b  = bt0 >> 11;                // same for both rows

    if (blockIdx.x < 8) {
        // ===== Q tiles: per-head RMS norm + rope -> g_qh/g_ql =====
        float s00 = 0, s01 = 0, s10 = 0, s11 = 0;   // [row][head]
        #pragma unroll
        for (int fn = 0; fn < 16; fn++) {
            float a0 = acc[fn][0]*acc[fn][0] + acc[fn][1]*acc[fn][1];
            float a1 = acc[fn][2]*acc[fn][2] + acc[fn][3]*acc[fn][3];
            if (fn < 8) { s00 += a0; s10 += a1; } else { s01 += a0; s11 += a1; }
        }
        #pragma unroll
        for (int o = 1; o <= 2; o <<= 1) {
            s00 += __shfl_xor_sync(~0u, s00, o);
            s01 += __shfl_xor_sync(~0u, s01, o);
            s10 += __shfl_xor_sync(~0u, s10, o);
            s11 += __shfl_xor_sync(~0u, s11, o);
        }
        float n00 = rsqrtf(s00 * (1.f/HD) + 1e-6f), n01 = rsqrtf(s01 * (1.f/HD) + 1e-6f);
        float n10 = rsqrtf(s10 * (1.f/HD) + 1e-6f), n11 = rsqrtf(s11 * (1.f/HD) + 1e-6f);
        #pragma unroll
        for (int fn = 0; fn < 16; fn++) {
            int d0 = (fn & 7) * 8 + c2;
            float w0 = qw[d0], w1 = qw[d0 + 1];
            float f0 = (fn < 8) ? n00 : n01, f1 = (fn < 8) ? n10 : n11;
            acc[fn][0] *= f0 * w0; acc[fn][1] *= f0 * w1;
            acc[fn][2] *= f1 * w0; acc[fn][3] *= f1 * w1;
        }
        // rope on fn {6,7} and {14,15}
        float c00 = cosp[t0*8 + c2], c01 = cosp[t0*8 + c2 + 1];
        float sn00 = sinp[t0*8 + c2], sn01 = sinp[t0*8 + c2 + 1];
        float c10 = cosp[t1*8 + c2], c11 = cosp[t1*8 + c2 + 1];
        float sn10 = sinp[t1*8 + c2], sn11 = sinp[t1*8 + c2 + 1];
        #pragma unroll
        for (int hp = 0; hp < 2; hp++) {
            int f1i = hp * 8 + 6, f2i = f1i + 1;
            float x10 = acc[f1i][0], x11 = acc[f1i][1], x12 = acc[f1i][2], x13 = acc[f1i][3];
            float x20 = acc[f2i][0], x21 = acc[f2i][1], x22 = acc[f2i][2], x23 = acc[f2i][3];
            acc[f1i][0] = x10*c00 - x20*sn00; acc[f1i][1] = x11*c01 - x21*sn01;
            acc[f1i][2] = x12*c10 - x22*sn10; acc[f1i][3] = x13*c11 - x23*sn11;
            acc[f2i][0] = x20*c00 + x10*sn00; acc[f2i][1] = x21*c01 + x11*sn01;
            acc[f2i][2] = x22*c10 + x12*sn10; acc[f2i][3] = x23*c11 + x13*sn11;
        }
        // store hi/lo
        #pragma unroll
        for (int fn = 0; fn < 16; fn++) {
            int hg = (n0 >> 6) + (fn >> 3);
            int d  = (fn & 7) * 8 + c2;
            size_t a0 = (((size_t)(b * NH + hg)) * TT + t0) * HD + d;
            size_t a1 = (((size_t)(b * NH + hg)) * TT + t1) * HD + d;
            *(uint32_t*)(g_qh + a0) = packh(acc[fn][0], acc[fn][1]);
            *(uint32_t*)(g_ql + a0) = pack_lo_resid(acc[fn][0], acc[fn][1]);
            *(uint32_t*)(g_qh + a1) = packh(acc[fn][2], acc[fn][3]);
            *(uint32_t*)(g_ql + a1) = pack_lo_resid(acc[fn][2], acc[fn][3]);
        }
    } else if (blockIdx.x == 8) {
        // ===== latent tile: RMS over 128 -> lth fp16 =====
        float s0 = 0, s1 = 0;
        #pragma unroll
        for (int fn = 0; fn < 16; fn++) {
            s0 += acc[fn][0]*acc[fn][0] + acc[fn][1]*acc[fn][1];
            s1 += acc[fn][2]*acc[fn][2] + acc[fn][3]*acc[fn][3];
        }
        #pragma unroll
        for (int o = 1; o <= 2; o <<= 1) {
            s0 += __shfl_xor_sync(~0u, s0, o);
            s1 += __shfl_xor_sync(~0u, s1, o);
        }
        float n0f = rsqrtf(s0 * (1.f/RR) + 1e-6f), n1f = rsqrtf(s1 * (1.f/RR) + 1e-6f);
        #pragma unroll
        for (int fn = 0; fn < 16; fn++) {
            int r = fn * 8 + c2;
            float w0 = kvaw[r], w1 = kvaw[r + 1];
            *(uint32_t*)(g_lth + (size_t)bt0 * RR + r) =
                packh(acc[fn][0] * n0f * w0, acc[fn][1] * n0f * w1);
            *(uint32_t*)(g_lth + (size_t)bt1 * RR + r) =
                packh(acc[fn][2] * n1f * w0, acc[fn][3] * n1f * w1);
        }
    } else {
        // ===== rope tile (cols 1152..1167): rope k_rope, broadcast to heads =====
        float c00 = cosp[t0*8 + c2], c01 = cosp[t0*8 + c2 + 1];
        float sn00 = sinp[t0*8 + c2], sn01 = sinp[t0*8 + c2 + 1];
        float c10 = cosp[t1*8 + c2], c11 = cosp[t1*8 + c2 + 1];
        float sn10 = sinp[t1*8 + c2], sn11 = sinp[t1*8 + c2 + 1];
        float x10 = acc[0][0], x11 = acc[0][1], x12 = acc[0][2], x13 = acc[0][3];
        float x20 = acc[1][0], x21 = acc[1][1], x22 = acc[1][2], x23 = acc[1][3];
        float o10 = x10*c00 - x20*sn00, o11 = x11*c01 - x21*sn01;
        float o12 = x12*c10 - x22*sn10, o13 = x13*c11 - x23*sn11;
        float o20 = x20*c00 + x10*sn00, o21 = x21*c01 + x11*sn01;
        float o22 = x22*c10 + x12*sn10, o23 = x23*c11 + x13*sn11;
        uint32_t h1a = packh(o10, o11), l1a = pack_lo_resid(o10, o11);
        uint32_t h1b = packh(o12, o13), l1b = pack_lo_resid(o12, o13);
        uint32_t h2a = packh(o20, o21), l2a = pack_lo_resid(o20, o21);
        uint32_t h2b = packh(o22, o23), l2b = pack_lo_resid(o22, o23);
        #pragma unroll
        for (int h = 0; h < NH; h++) {
            size_t a0 = (((size_t)(b * NH + h)) * TT + t0) * HD + 48 + c2;
            size_t a1 = (((size_t)(b * NH + h)) * TT + t1) * HD + 48 + c2;
            *(uint32_t*)(g_kh + a0)     = h1a; *(uint32_t*)(g_kl + a0)     = l1a;
            *(uint32_t*)(g_kh + a0 + 8) = h2a; *(uint32_t*)(g_kl + a0 + 8) = l2a;
            *(uint32_t*)(g_kh + a1)     = h1b; *(uint32_t*)(g_kl + a1)     = l1b;
            *(uint32_t*)(g_kh + a1 + 8) = h2b; *(uint32_t*)(g_kl + a1 + 8) = l2b;
        }
    }
}

// ======================= kvb GEMM with fused scatter epilogue =======================
// C = lth @ (Wbh+Wbl)^T ; scatter k_nope(hi/lo) + v(hi) to [bh][t][d].
__global__ __launch_bounds__(256, 2) void kvb_gemm()
{
    extern __shared__ __align__(16) char smem[];
    const int tid = threadIdx.x, wid = tid >> 5, lane = tid & 31;
    const int warp_m = wid >> 2, warp_n = wid & 3;
    const int m0 = blockIdx.y * 128, n0 = blockIdx.x * 128;
    uint32_t smem_base = smem_u32(smem);

    const char* base[3] = { (const char*)(g_lth + (size_t)m0 * RR),
                            (const char*)(g_Wbh + (size_t)n0 * RR),
                            (const char*)(g_Wbl + (size_t)n0 * RR) };
    const size_t ldbytes = (size_t)RR * 2;
    const int nch = RR >> 5;   // 4

    const int lm = lane & 15, lh = lane >> 4;
    const int g = lane >> 3, r = lane & 7;
    const int r4 = lane >> 2, c2 = (lane & 3) * 2;

    float acc[4][4][4];
    #pragma unroll
    for (int i = 0; i < 4; i++)
        #pragma unroll
        for (int j = 0; j < 4; j++)
            #pragma unroll
            for (int e = 0; e < 4; e++) acc[i][j][e] = 0.f;

    GEMM_LOAD_CHUNK(0, 0);
    GEMM_LOAD_CHUNK(1, 1);

    for (int ch = 0; ch < nch; ch++) {
        asm volatile("cp.async.wait_group 1;");
        __syncthreads();
        if (ch + 2 < nch) { GEMM_LOAD_CHUNK(ch + 2, (ch + 2) % NSTAGE); }
        else asm volatile("cp.async.commit_group;");
        const uint32_t smA  = smem_base + (ch % NSTAGE) * GBUF_B;
        const uint32_t smBh = smA + GTILE_B;
        const uint32_t smBl = smBh + GTILE_B;
        #pragma unroll
        for (int k16 = 0; k16 < 2; k16++) {
            uint32_t a[4][4];
            #pragma unroll
            for (int fm = 0; fm < 4; fm++)
                ldsm4(a[fm], smA + ((warp_m * 64 + fm * 16 + lm) * GPAD
                                    + k16 * 16 + lh * 8) * 2);
            uint32_t bh[4][2], bl[4][2];
            #pragma unroll
            for (int fp = 0; fp < 2; fp++) {
                int row = warp_n * 32 + fp * 16 + ((g >> 1) << 3) + r;
                int off = (row * GPAD + (g & 1) * 8 + k16 * 16) * 2;
                uint32_t t4[4];
                ldsm4(t4, smBh + off);
                bh[fp*2][0]=t4[0]; bh[fp*2][1]=t4[1]; bh[fp*2+1][0]=t4[2]; bh[fp*2+1][1]=t4[3];
                ldsm4(t4, smBl + off);
                bl[fp*2][0]=t4[0]; bl[fp*2][1]=t4[1]; bl[fp*2+1][0]=t4[2]; bl[fp*2+1][1]=t4[3];
            }
            #pragma unroll
            for (int fm = 0; fm < 4; fm++)
                #pragma unroll
                for (int fn = 0; fn < 4; fn++) {
                    mma16816(acc[fm][fn], a[fm], bh[fn]);
                    mma16816(acc[fm][fn], a[fm], bl[fn]);
                }
        }
    }

    // scatter epilogue
    #pragma unroll
    for (int fm = 0; fm < 4; fm++) {
        int bt0 = m0 + warp_m * 64 + fm * 16 + r4;
        int bt1 = bt0 + 8;
        int t0 = bt0 & (TT - 1), t1 = bt1 & (TT - 1);
        int b  = bt0 >> 11;
        #pragma unroll
        for (int fn = 0; fn < 4; fn++) {
            int n = n0 + warp_n * 32 + fn * 8 + c2;
            int h = n / 112, rr2 = n % 112;
            size_t hb = (size_t)(b * NH + h) * TT;
            if (rr2 < NOPE) {
                size_t a0 = (hb + t0) * HD + rr2, a1 = (hb + t1) * HD + rr2;
                *(uint32_t*)(g_kh + a0) = packh(acc[fm][fn][0], acc[fm][fn][1]);
                *(uint32_t*)(g_kl + a0) = pack_lo_resid(acc[fm][fn][0], acc[fm][fn][1]);
                *(uint32_t*)(g_kh + a1) = packh(acc[fm][fn][2], acc[fm][fn][3]);
                *(uint32_t*)(g_kl + a1) = pack_lo_resid(acc[fm][fn][2], acc[fm][fn][3]);
            } else {
                int d = rr2 - NOPE;
                size_t a0 = (hb + t0) * VD + d, a1 = (hb + t1) * VD + d;
                *(uint32_t*)(g_vh + a0) = packh(acc[fm][fn][0], acc[fm][fn][1]);
                *(uint32_t*)(g_vh + a1) = packh(acc[fm][fn][2], acc[fm][fn][3]);
            }
        }
    }
}

// ======================= Wo GEMM (fp32 out) =======================
__global__ __launch_bounds__(256, 2) void wo_gemm(float* __restrict__ C)
{
    extern __shared__ __align__(16) char smem[];
    const int tid = threadIdx.x, wid = tid >> 5, lane = tid & 31;
    const int warp_m = wid >> 2, warp_n = wid & 3;
    const int m0 = blockIdx.y * 128, n0 = blockIdx.x * 128;
    uint32_t smem_base = smem_u32(smem);

    const char* base[3] = { (const char*)(g_aoh + (size_t)m0 * DD),
                            (const char*)(g_Woh + (size_t)n0 * DD),
                            (const char*)(g_Wol + (size_t)n0 * DD) };
    const size_t ldbytes = (size_t)DD * 2;
    const int nch = DD >> 5;

    const int lm = lane & 15, lh = lane >> 4;
    const int g = lane >> 3, r = lane & 7;

    float acc[4][4][4];
    #pragma unroll
    for (int i = 0; i < 4; i++)
        #pragma unroll
        for (int j = 0; j < 4; j++)
            #pragma unroll
            for (int e = 0; e < 4; e++) acc[i][j][e] = 0.f;

    GEMM_LOAD_CHUNK(0, 0);
    GEMM_LOAD_CHUNK(1, 1);

    for (int ch = 0; ch < nch; ch++) {
        asm volatile("cp.async.wait_group 1;");
        __syncthreads();
        if (ch + 2 < nch) { GEMM_LOAD_CHUNK(ch + 2, (ch + 2) % NSTAGE); }
        else asm volatile("cp.async.commit_group;");
        const uint32_t smA  = smem_base + (ch % NSTAGE) * GBUF_B;
        const uint32_t smBh = smA + GTILE_B;
        const uint32_t smBl = smBh + GTILE_B;
        #pragma unroll
        for (int k16 = 0; k16 < 2; k16++) {
            uint32_t a[4][4];
            #pragma unroll
            for (int fm = 0; fm < 4; fm++)
                ldsm4(a[fm], smA + ((warp_m * 64 + fm * 16 + lm) * GPAD
                                    + k16 * 16 + lh * 8) * 2);
            uint32_t bh[4][2], bl[4][2];
            #pragma unroll
            for (int fp = 0; fp < 2; fp++) {
                int row = warp_n * 32 + fp * 16 + ((g >> 1) << 3) + r;
                int off = (row * GPAD + (g & 1) * 8 + k16 * 16) * 2;
                uint32_t t4[4];
                ldsm4(t4, smBh + off);
                bh[fp*2][0]=t4[0]; bh[fp*2][1]=t4[1]; bh[fp*2+1][0]=t4[2]; bh[fp*2+1][1]=t4[3];
                ldsm4(t4, smBl + off);
                bl[fp*2][0]=t4[0]; bl[fp*2][1]=t4[1]; bl[fp*2+1][0]=t4[2]; bl[fp*2+1][1]=t4[3];
            }
            #pragma unroll
            for (int fm = 0; fm < 4; fm++)
                #pragma unroll
                for (int fn = 0; fn < 4; fn++) {
                    mma16816(acc[fm][fn], a[fm], bh[fn]);
                    mma16816(acc[fm][fn], a[fm], bl[fn]);
                }
        }
    }

    const int r4 = lane >> 2, c2 = (lane & 3) * 2;
    #pragma unroll
    for (int fm = 0; fm < 4; fm++) {
        #pragma unroll
        for (int fn = 0; fn < 4; fn++) {
            int m = m0 + warp_m * 64 + fm * 16 + r4;
            int n = n0 + warp_n * 32 + fn * 8 + c2;
            *(float2*)&C[(size_t)m * DD + n] = make_float2(acc[fm][fn][0], acc[fm][fn][1]);
            *(float2*)&C[(size_t)(m + 8) * DD + n] = make_float2(acc[fm][fn][2], acc[fm][fn][3]);
        }
    }
}

// ---------------- flash attention (fp16: S 3-term, PV 2-term) ----------------
#define FPAD 72

__global__ __launch_bounds__(256) void flash_mma()
{
    __shared__ __align__(16) __half sm[2 * 128 * FPAD];

    const int tid = threadIdx.x, wid = tid >> 5, lane = tid & 31;
    const int bh = blockIdx.y;
    const int b = bh >> 4, h = bh & (NH - 1);
    const int qtile = gridDim.x - 1 - blockIdx.x;
    const int qb = qtile * 128;
    const uint32_t sb = smem_u32(sm);

    const int lm = lane & 15, lh = lane >> 4;
    const int g = lane >> 3, r8 = lane & 7;
    const int r4 = lane >> 2, c2 = (lane & 3) * 2;

    {
        const __half* qhp = g_qh + ((size_t)bh * TT + qb) * HD;
        const __half* qlp = g_ql + ((size_t)bh * TT + qb) * HD;
        for (int i = tid; i < 128 * 8; i += 256) {
            int r = i >> 3, s = i & 7;
            *(uint4*)(sm + r * FPAD + s * 8) = *(const uint4*)(qhp + r * 64 + s * 8);
            *(uint4*)(sm + 128 * FPAD + r * FPAD + s * 8) = *(const uint4*)(qlp + r * 64 + s * 8);
        }
    }
    __syncthreads();

    uint32_t qh[4][4], ql[4][4];
    #pragma unroll
    for (int ks = 0; ks < 4; ks++) {
        uint32_t addr = sb + ((wid * 16 + lm) * FPAD + ks * 16 + lh * 8) * 2;
        ldsm4(qh[ks], addr);
        ldsm4(ql[ks], addr + 128 * FPAD * 2);
    }

    float o[8][4];
    #pragma unroll
    for (int i = 0; i < 8; i++)
        #pragma unroll
        for (int e = 0; e < 4; e++) o[i][e] = 0.f;
    float mrow[2] = { -1e30f, -1e30f };
    float lsum[2] = { 0.f, 0.f };

    const __half* khb = g_kh + (size_t)bh * TT * HD;
    const __half* klb = g_kl + (size_t)bh * TT * HD;
    const __half* vhb = g_vh + (size_t)bh * TT * VD;

    const int ntiles = qtile * 2 + 2;
    const float scale = 0.125f;
    const int q0 = qb + wid * 16 + r4;
    const int q1 = q0 + 8;

    const uint32_t oKl = 64 * FPAD * 2;
    const uint32_t oVh = 2 * 64 * FPAD * 2;

    for (int it = 0; it < ntiles; it++) {
        const int j0 = it * 64;
        __syncthreads();
        for (int i = tid; i < 64 * 8; i += 256) {
            int r = i >> 3, s = i & 7;
            size_t gsrc = (size_t)(j0 + r) * 64 + s * 8;
            int dsh = r * FPAD + s * 8;
            *(uint4*)(sm + dsh) = *(const uint4*)(khb + gsrc);
            *(uint4*)(sm + 64 * FPAD + dsh) = *(const uint4*)(klb + gsrc);
            *(uint4*)(sm + 2 * 64 * FPAD + dsh) = *(const uint4*)(vhb + gsrc);
        }
        __syncthreads();

        float s[8][4];
        #pragma unroll
        for (int i = 0; i < 8; i++)
            #pragma unroll
            for (int e = 0; e < 4; e++) s[i][e] = 0.f;

        #pragma unroll
        for (int fp = 0; fp < 4; fp++) {
            const int krow = fp * 16 + ((g >> 1) << 3) + r8;
            const int kcol = (g & 1) * 8;
            #pragma unroll
            for (int ks = 0; ks < 4; ks++) {
                uint32_t addr = sb + (krow * FPAD + kcol + ks * 16) * 2;
                uint32_t bhf[4], blf[4];
                ldsm4(bhf, addr);
                ldsm4(blf, addr + oKl);
                mma16816(s[fp*2],   qh[ks], bhf);
                mma16816(s[fp*2],   qh[ks], blf);
                mma16816(s[fp*2],   ql[ks], bhf);
                mma16816(s[fp*2+1], qh[ks], bhf + 2);
                mma16816(s[fp*2+1], qh[ks], blf + 2);
                mma16816(s[fp*2+1], ql[ks], bhf + 2);
            }
        }

        const bool need_mask = (it >= ntiles - 2);
        #pragma unroll
        for (int fn = 0; fn < 8; fn++) {
            #pragma unroll
            for (int e = 0; e < 4; e++) {
                float x = s[fn][e] * scale;
                if (need_mask) {
                    int kv = j0 + fn * 8 + c2 + (e & 1);
                    int qq = (e < 2) ? q0 : q1;
                    if (kv > qq) x = -1e30f;
                }
                s[fn][e] = x;
            }
        }

        float tm0 = -1e30f, tm1 = -1e30f;
        #pragma unroll
        for (int fn = 0; fn < 8; fn++) {
            tm0 = fmaxf(tm0, fmaxf(s[fn][0], s[fn][1]));
            tm1 = fmaxf(tm1, fmaxf(s[fn][2], s[fn][3]));
        }
        tm0 = fmaxf(tm0, __shfl_xor_sync(~0u, tm0, 1));
        tm0 = fmaxf(tm0, __shfl_xor_sync(~0u, tm0, 2));
        tm1 = fmaxf(tm1, __shfl_xor_sync(~0u, tm1, 1));
        tm1 = fmaxf(tm1, __shfl_xor_sync(~0u, tm1, 2));

        float mn0 = fmaxf(mrow[0], tm0), mn1 = fmaxf(mrow[1], tm1);
        float cr0 = __expf(mrow[0] - mn0), cr1 = __expf(mrow[1] - mn1);
        mrow[0] = mn0; mrow[1] = mn1;
        lsum[0] *= cr0; lsum[1] *= cr1;
        #pragma unroll
        for (int fn = 0; fn < 8; fn++) {
            o[fn][0] *= cr0; o[fn][1] *= cr0;
            o[fn][2] *= cr1; o[fn][3] *= cr1;
        }

        #pragma unroll
        for (int fn = 0; fn < 8; fn++) {
            s[fn][0] = __expf(s[fn][0] - mn0);
            s[fn][1] = __expf(s[fn][1] - mn0);
            s[fn][2] = __expf(s[fn][2] - mn1);
            s[fn][3] = __expf(s[fn][3] - mn1);
            lsum[0] += s[fn][0] + s[fn][1];
            lsum[1] += s[fn][2] + s[fn][3];
        }

        #pragma unroll
        for (int ks = 0; ks < 4; ks++) {
            float p0[4] = { s[ks*2][0], s[ks*2][1], s[ks*2][2], s[ks*2][3] };
            float p1[4] = { s[ks*2+1][0], s[ks*2+1][1], s[ks*2+1][2], s[ks*2+1][3] };
            uint32_t aph[4], apl[4];
            aph[0] = packh(p0[0], p0[1]); aph[1] = packh(p0[2], p0[3]);
            aph[2] = packh(p1[0], p1[1]); aph[3] = packh(p1[2], p1[3]);
            apl[0] = pack_lo_resid(p0[0], p0[1]);
            apl[1] = pack_lo_resid(p0[2], p0[3]);
            apl[2] = pack_lo_resid(p1[0], p1[1]);
            apl[3] = pack_lo_resid(p1[2], p1[3]);

            const int vrow = ks * 16 + (g & 1) * 8 + r8;
            #pragma unroll
            for (int np = 0; np < 4; np++) {
                const int vcol = np * 16 + lh * 8;
                uint32_t addr = sb + oVh + (vrow * FPAD + vcol) * 2;
                uint32_t bvh[4];
                ldsm4t(bvh, addr);
                mma16816(o[np*2],   aph, bvh);
                mma16816(o[np*2],   apl, bvh);
                mma16816(o[np*2+1], aph, bvh + 2);
                mma16816(o[np*2+1], apl, bvh + 2);
            }
        }
    }

    lsum[0] += __shfl_xor_sync(~0u, lsum[0], 1);
    lsum[0] += __shfl_xor_sync(~0u, lsum[0], 2);
    lsum[1] += __shfl_xor_sync(~0u, lsum[1], 1);
    lsum[1] += __shfl_xor_sync(~0u, lsum[1], 2);
    const float inv0 = 1.f / lsum[0], inv1 = 1.f / lsum[1];

    __half* ob0 = g_aoh + ((size_t)(b * TT + q0)) * (NH * VD) + h * VD;
    __half* ob1 = g_aoh + ((size_t)(b * TT + q1)) * (NH * VD) + h * VD;
    #pragma unroll
    for (int fn = 0; fn < 8; fn++) {
        *(uint32_t*)(ob0 + fn * 8 + c2) = packh(o[fn][0] * inv0, o[fn][1] * inv0);
        *(uint32_t*)(ob1 + fn * 8 + c2) = packh(o[fn][2] * inv1, o[fn][3] * inv1);
    }
}

// ---------------- launch ----------------
extern "C" void kernel_launch(void* const* d_in, const int* in_sizes, int n_in,
                              void* d_out, int out_size)
{
    const float* x    = (const float*)d_in[0];
    const float* cosp = (const float*)d_in[1];
    const float* sinp = (const float*)d_in[2];
    const float* Wq   = (const float*)d_in[3];
    const float* qw   = (const float*)d_in[4];
    const float* Wkva = (const float*)d_in[5];
    const float* kvaw = (const float*)d_in[6];
    const float* Wkvb = (const float*)d_in[7];
    const float* Wo   = (const float*)d_in[8];
    float* out = (float*)d_out;

    cudaFuncSetAttribute(proj1_gemm, cudaFuncAttributeMaxDynamicSharedMemorySize, NSTAGE * GBUF_B);
    cudaFuncSetAttribute(kvb_gemm,   cudaFuncAttributeMaxDynamicSharedMemorySize, NSTAGE * GBUF_B);
    cudaFuncSetAttribute(wo_gemm,    cudaFuncAttributeMaxDynamicSharedMemorySize, NSTAGE * GBUF_B);

    // 1) conversions
    cvt_all<<<(QTOT + 255) / 256, 256>>>(x, Wq, Wkva, Wkvb, Wo);

    // 2) merged q/kva projection with fused norm+rope epilogue
    {
        dim3 g(W1_ROWS / 128, MTOT / 128);   // (10, 32)
        proj1_gemm<<<g, 256, NSTAGE * GBUF_B>>>(cosp, sinp, qw, kvaw);
    }

    // 3) kvb projection with fused scatter epilogue
    {
        dim3 g(KVB_N / 128, MTOT / 128);     // (14, 32)
        kvb_gemm<<<g, 256, NSTAGE * GBUF_B>>>();
    }

    // 4) flash attention -> fp16 aoh
    {
        dim3 g(TT / 128, BB * NH);
        flash_mma<<<g, 256>>>();
    }

    // 5) output projection
    {
        dim3 g(DD / 128, MTOT / 128);
        wo_gemm<<<g, 256, NSTAGE * GBUF_B>>>(out);
    }
}

// round 9
// speedup vs baseline: 4.4882x; 1.1614x over previous
#include <cuda_runtime.h>
#include <cuda_fp16.h>
#include <math.h>
#include <cstdint>

#define BB 2
#define TT 2048
#define DD 1024
#define NH 16
#define HD 64      // NOPE_D + ROPE_D
#define NOPE 48
#define ROPED 16
#define RR 128
#define VD 64
#define KVB_N (NH * (NOPE + VD))   // 1792
#define MTOT (BB * TT)             // 4096
#define W1_ROWS 1280               // 1024 (Wq) + 128 (latent) + 16 (rope) + 112 pad

// ---------------- device scratch ----------------
__device__ __align__(256) __half g_qh[BB*NH*TT*HD], g_ql[BB*NH*TT*HD];
__device__ __align__(256) __half g_kh[BB*NH*TT*HD], g_kl[BB*NH*TT*HD];
__device__ __align__(256) __half g_vh[BB*NH*TT*VD];

__device__ __align__(256) __half g_xh [MTOT * DD];
__device__ __align__(256) __half g_W1h[W1_ROWS * DD], g_W1l[W1_ROWS * DD];
__device__ __align__(256) __half g_Wbh[KVB_N * RR],   g_Wbl[KVB_N * RR];
__device__ __align__(256) __half g_Woh[DD * DD],      g_Wol[DD * DD];
__device__ __align__(256) __half g_lth[MTOT * RR];
__device__ __align__(256) __half g_aoh[MTOT * DD];

// ======================= helpers =======================
__device__ __forceinline__ uint32_t smem_u32(const void* p) {
    uint32_t a;
    asm("{ .reg .u64 t; cvta.to.shared.u64 t, %1; cvt.u32.u64 %0, t; }" : "=r"(a) : "l"(p));
    return a;
}
__device__ __forceinline__ void mma16816(float* c, const uint32_t* a, const uint32_t* b) {
    asm volatile("mma.sync.aligned.m16n8k16.row.col.f32.f16.f16.f32 "
        "{%0,%1,%2,%3}, {%4,%5,%6,%7}, {%8,%9}, {%0,%1,%2,%3};"
        : "+f"(c[0]), "+f"(c[1]), "+f"(c[2]), "+f"(c[3])
        : "r"(a[0]), "r"(a[1]), "r"(a[2]), "r"(a[3]), "r"(b[0]), "r"(b[1]));
}
__device__ __forceinline__ void ldsm4(uint32_t* r, uint32_t addr) {
    asm volatile("ldmatrix.sync.aligned.m8n8.x4.shared.b16 {%0,%1,%2,%3}, [%4];"
        : "=r"(r[0]), "=r"(r[1]), "=r"(r[2]), "=r"(r[3]) : "r"(addr));
}
__device__ __forceinline__ void ldsm4t(uint32_t* r, uint32_t addr) {
    asm volatile("ldmatrix.sync.aligned.m8n8.x4.trans.shared.b16 {%0,%1,%2,%3}, [%4];"
        : "=r"(r[0]), "=r"(r[1]), "=r"(r[2]), "=r"(r[3]) : "r"(addr));
}
__device__ __forceinline__ uint32_t packh(float lo, float hi) {
    uint32_t d;
    asm("cvt.rn.f16x2.f32 %0, %1, %2;" : "=r"(d) : "f"(hi), "f"(lo));
    return d;
}
__device__ __forceinline__ uint32_t pack_lo_resid(float v0, float v1) {
    float h0 = __half2float(__float2half(v0));
    float h1 = __half2float(__float2half(v1));
    return packh(v0 - h0, v1 - h1);
}

// ======================= fused conversions =======================
#define QX  (MTOT * DD / 4)
#define QW1 (W1_ROWS * DD / 4)
#define QWB (KVB_N * RR / 4)
#define QWO (DD * DD / 4)
#define QTOT (QX + QW1 + QWB + QWO)

__device__ __forceinline__ void do_hl(const float* s, __half* dh, __half* dl, int e) {
    float4 v = *(const float4*)(s + e);
    __half h0 = __float2half(v.x), h1 = __float2half(v.y);
    __half h2 = __float2half(v.z), h3 = __float2half(v.w);
    ((__half2*)(dh + e))[0] = __half2(h0, h1);
    ((__half2*)(dh + e))[1] = __half2(h2, h3);
    ((__half2*)(dl + e))[0] = __half2(__float2half(v.x - __half2float(h0)),
                                      __float2half(v.y - __half2float(h1)));
    ((__half2*)(dl + e))[1] = __half2(__float2half(v.z - __half2float(h2)),
                                      __float2half(v.w - __half2float(h3)));
}

__global__ __launch_bounds__(256) void cvt_all(
    const float* __restrict__ x,    const float* __restrict__ Wq,
    const float* __restrict__ Wkva, const float* __restrict__ Wkvb,
    const float* __restrict__ Wo)
{
    int qi = blockIdx.x * blockDim.x + threadIdx.x;
    if (qi >= QTOT) return;
    if (qi < QX) {
        int e = qi * 4;
        float4 v = *(const float4*)(x + e);
        ((__half2*)(g_xh + e))[0] = __half2(__float2half(v.x), __float2half(v.y));
        ((__half2*)(g_xh + e))[1] = __half2(__float2half(v.z), __float2half(v.w));
        return;
    }
    qi -= QX;
    if (qi < QW1) {
        int e = qi * 4;
        if (e < DD * DD) { do_hl(Wq, g_W1h, g_W1l, e); }
        else if (e < (DD + 144) * DD) {
            float4 v = *(const float4*)(Wkva + (e - DD * DD));
            __half h0 = __float2half(v.x), h1 = __float2half(v.y);
            __half h2 = __float2half(v.z), h3 = __float2half(v.w);
            ((__half2*)(g_W1h + e))[0] = __half2(h0, h1);
            ((__half2*)(g_W1h + e))[1] = __half2(h2, h3);
            ((__half2*)(g_W1l + e))[0] = __half2(__float2half(v.x - __half2float(h0)),
                                                 __float2half(v.y - __half2float(h1)));
            ((__half2*)(g_W1l + e))[1] = __half2(__float2half(v.z - __half2float(h2)),
                                                 __float2half(v.w - __half2float(h3)));
        } else {
            __half2 z(__half(0.f), __half(0.f));
            ((__half2*)(g_W1h + e))[0] = z; ((__half2*)(g_W1h + e))[1] = z;
            ((__half2*)(g_W1l + e))[0] = z; ((__half2*)(g_W1l + e))[1] = z;
        }
        return;
    }
    qi -= QW1;
    if (qi < QWB) { do_hl(Wkvb, g_Wbh, g_Wbl, qi * 4); return; }
    qi -= QWB;
    do_hl(Wo, g_Woh, g_Wol, qi * 4);
}

// ======================= shared GEMM plumbing =======================
#define GPAD 40
#define GTILE_B (128 * GPAD * 2)
#define GBUF_B  (3 * GTILE_B)
#define NSTAGE 3

#define GEMM_LOAD_CHUNK(ch, buf)                                               \
    do {                                                                       \
        const int k0b = ((ch) << 5) * 2;                                       \
        _Pragma("unroll")                                                      \
        for (int it = 0; it < 6; it++) {                                       \
            int i = tid + it * 256;                                            \
            int mat = i >> 9, rem = i & 511;                                   \
            int row = rem >> 2, seg = rem & 3;                                 \
            const char* src = base[mat] + (size_t)row * ldbytes + k0b + seg * 16; \
            uint32_t dst = smem_base + (buf) * GBUF_B + mat * GTILE_B          \
                         + (row * GPAD + seg * 8) * 2;                         \
            asm volatile("cp.async.cg.shared.global [%0], [%1], 16;" :: "r"(dst), "l"(src)); \
        }                                                                      \
        asm volatile("cp.async.commit_group;");                                \
    } while (0)

// ======================= proj1 =======================
__global__ __launch_bounds__(256, 2) void proj1_gemm(
    const float* __restrict__ cosp, const float* __restrict__ sinp,
    const float* __restrict__ qw,   const float* __restrict__ kvaw)
{
    extern __shared__ __align__(16) char smem[];
    const int tid = threadIdx.x, wid = tid >> 5, lane = tid & 31;
    const int m0 = blockIdx.y * 128, n0 = blockIdx.x * 128;
    uint32_t smem_base = smem_u32(smem);

    const char* base[3] = { (const char*)(g_xh  + (size_t)m0 * DD),
                            (const char*)(g_W1h + (size_t)n0 * DD),
                            (const char*)(g_W1l + (size_t)n0 * DD) };
    const size_t ldbytes = (size_t)DD * 2;
    const int nch = DD >> 5;

    const int lm = lane & 15, lh = lane >> 4;
    const int g = lane >> 3, r8 = lane & 7;
    const int r4 = lane >> 2, c2 = (lane & 3) * 2;

    float acc[16][4];
    #pragma unroll
    for (int i = 0; i < 16; i++)
        #pragma unroll
        for (int e = 0; e < 4; e++) acc[i][e] = 0.f;

    GEMM_LOAD_CHUNK(0, 0);
    GEMM_LOAD_CHUNK(1, 1);

    for (int ch = 0; ch < nch; ch++) {
        asm volatile("cp.async.wait_group 1;");
        __syncthreads();
        if (ch + 2 < nch) { GEMM_LOAD_CHUNK(ch + 2, (ch + 2) % NSTAGE); }
        else asm volatile("cp.async.commit_group;");
        const uint32_t smA  = smem_base + (ch % NSTAGE) * GBUF_B;
        const uint32_t smBh = smA + GTILE_B;
        const uint32_t smBl = smBh + GTILE_B;
        #pragma unroll
        for (int k16 = 0; k16 < 2; k16++) {
            uint32_t a[4];
            ldsm4(a, smA + ((wid * 16 + lm) * GPAD + k16 * 16 + lh * 8) * 2);
            #pragma unroll
            for (int fp = 0; fp < 8; fp++) {
                int row = fp * 16 + ((g >> 1) << 3) + r8;
                int off = (row * GPAD + (g & 1) * 8 + k16 * 16) * 2;
                uint32_t t4[4];
                ldsm4(t4, smBh + off);
                mma16816(acc[fp*2],   a, t4);
                mma16816(acc[fp*2+1], a, t4 + 2);
                ldsm4(t4, smBl + off);
                mma16816(acc[fp*2],   a, t4);
                mma16816(acc[fp*2+1], a, t4 + 2);
            }
        }
    }

    const int bt0 = m0 + wid * 16 + r4;
    const int bt1 = bt0 + 8;
    const int t0 = bt0 & (TT - 1), t1 = bt1 & (TT - 1);
    const int b  = bt0 >> 11;

    if (blockIdx.x < 8) {
        float s00 = 0, s01 = 0, s10 = 0, s11 = 0;
        #pragma unroll
        for (int fn = 0; fn < 16; fn++) {
            float a0 = acc[fn][0]*acc[fn][0] + acc[fn][1]*acc[fn][1];
            float a1 = acc[fn][2]*acc[fn][2] + acc[fn][3]*acc[fn][3];
            if (fn < 8) { s00 += a0; s10 += a1; } else { s01 += a0; s11 += a1; }
        }
        #pragma unroll
        for (int o = 1; o <= 2; o <<= 1) {
            s00 += __shfl_xor_sync(~0u, s00, o);
            s01 += __shfl_xor_sync(~0u, s01, o);
            s10 += __shfl_xor_sync(~0u, s10, o);
            s11 += __shfl_xor_sync(~0u, s11, o);
        }
        float n00 = rsqrtf(s00 * (1.f/HD) + 1e-6f), n01 = rsqrtf(s01 * (1.f/HD) + 1e-6f);
        float n10 = rsqrtf(s10 * (1.f/HD) + 1e-6f), n11 = rsqrtf(s11 * (1.f/HD) + 1e-6f);
        #pragma unroll
        for (int fn = 0; fn < 16; fn++) {
            int d0 = (fn & 7) * 8 + c2;
            float w0 = qw[d0], w1 = qw[d0 + 1];
            float f0 = (fn < 8) ? n00 : n01, f1 = (fn < 8) ? n10 : n11;
            acc[fn][0] *= f0 * w0; acc[fn][1] *= f0 * w1;
            acc[fn][2] *= f1 * w0; acc[fn][3] *= f1 * w1;
        }
        float c00 = cosp[t0*8 + c2], c01 = cosp[t0*8 + c2 + 1];
        float sn00 = sinp[t0*8 + c2], sn01 = sinp[t0*8 + c2 + 1];
        float c10 = cosp[t1*8 + c2], c11 = cosp[t1*8 + c2 + 1];
        float sn10 = sinp[t1*8 + c2], sn11 = sinp[t1*8 + c2 + 1];
        #pragma unroll
        for (int hp = 0; hp < 2; hp++) {
            int f1i = hp * 8 + 6, f2i = f1i + 1;
            float x10 = acc[f1i][0], x11 = acc[f1i][1], x12 = acc[f1i][2], x13 = acc[f1i][3];
            float x20 = acc[f2i][0], x21 = acc[f2i][1], x22 = acc[f2i][2], x23 = acc[f2i][3];
            acc[f1i][0] = x10*c00 - x20*sn00; acc[f1i][1] = x11*c01 - x21*sn01;
            acc[f1i][2] = x12*c10 - x22*sn10; acc[f1i][3] = x13*c11 - x23*sn11;
            acc[f2i][0] = x20*c00 + x10*sn00; acc[f2i][1] = x21*c01 + x11*sn01;
            acc[f2i][2] = x22*c10 + x12*sn10; acc[f2i][3] = x23*c11 + x13*sn11;
        }
        #pragma unroll
        for (int fn = 0; fn < 16; fn++) {
            #pragma unroll
            for (int e = 0; e < 4; e++) acc[fn][e] *= 0.125f;
        }
        #pragma unroll
        for (int fn = 0; fn < 16; fn++) {
            int hg = (n0 >> 6) + (fn >> 3);
            int d  = (fn & 7) * 8 + c2;
            size_t a0 = (((size_t)(b * NH + hg)) * TT + t0) * HD + d;
            size_t a1 = (((size_t)(b * NH + hg)) * TT + t1) * HD + d;
            *(uint32_t*)(g_qh + a0) = packh(acc[fn][0], acc[fn][1]);
            *(uint32_t*)(g_ql + a0) = pack_lo_resid(acc[fn][0], acc[fn][1]);
            *(uint32_t*)(g_qh + a1) = packh(acc[fn][2], acc[fn][3]);
            *(uint32_t*)(g_ql + a1) = pack_lo_resid(acc[fn][2], acc[fn][3]);
        }
    } else if (blockIdx.x == 8) {
        float s0 = 0, s1 = 0;
        #pragma unroll
        for (int fn = 0; fn < 16; fn++) {
            s0 += acc[fn][0]*acc[fn][0] + acc[fn][1]*acc[fn][1];
            s1 += acc[fn][2]*acc[fn][2] + acc[fn][3]*acc[fn][3];
        }
        #pragma unroll
        for (int o = 1; o <= 2; o <<= 1) {
            s0 += __shfl_xor_sync(~0u, s0, o);
            s1 += __shfl_xor_sync(~0u, s1, o);
        }
        float n0f = rsqrtf(s0 * (1.f/RR) + 1e-6f), n1f = rsqrtf(s1 * (1.f/RR) + 1e-6f);
        #pragma unroll
        for (int fn = 0; fn < 16; fn++) {
            int r = fn * 8 + c2;
            float w0 = kvaw[r], w1 = kvaw[r + 1];
            *(uint32_t*)(g_lth + (size_t)bt0 * RR + r) =
                packh(acc[fn][0] * n0f * w0, acc[fn][1] * n0f * w1);
            *(uint32_t*)(g_lth + (size_t)bt1 * RR + r) =
                packh(acc[fn][2] * n1f * w0, acc[fn][3] * n1f * w1);
        }
    } else {
        float c00 = cosp[t0*8 + c2], c01 = cosp[t0*8 + c2 + 1];
        float sn00 = sinp[t0*8 + c2], sn01 = sinp[t0*8 + c2 + 1];
        float c10 = cosp[t1*8 + c2], c11 = cosp[t1*8 + c2 + 1];
        float sn10 = sinp[t1*8 + c2], sn11 = sinp[t1*8 + c2 + 1];
        float x10 = acc[0][0], x11 = acc[0][1], x12 = acc[0][2], x13 = acc[0][3];
        float x20 = acc[1][0], x21 = acc[1][1], x22 = acc[1][2], x23 = acc[1][3];
        float o10 = x10*c00 - x20*sn00, o11 = x11*c01 - x21*sn01;
        float o12 = x12*c10 - x22*sn10, o13 = x13*c11 - x23*sn11;
        float o20 = x20*c00 + x10*sn00, o21 = x21*c01 + x11*sn01;
        float o22 = x22*c10 + x12*sn10, o23 = x23*c11 + x13*sn11;
        uint32_t h1a = packh(o10, o11), l1a = pack_lo_resid(o10, o11);
        uint32_t h1b = packh(o12, o13), l1b = pack_lo_resid(o12, o13);
        uint32_t h2a = packh(o20, o21), l2a = pack_lo_resid(o20, o21);
        uint32_t h2b = packh(o22, o23), l2b = pack_lo_resid(o22, o23);
        #pragma unroll
        for (int h = 0; h < NH; h++) {
            size_t a0 = (((size_t)(b * NH + h)) * TT + t0) * HD + 48 + c2;
            size_t a1 = (((size_t)(b * NH + h)) * TT + t1) * HD + 48 + c2;
            *(uint32_t*)(g_kh + a0)     = h1a; *(uint32_t*)(g_kl + a0)     = l1a;
            *(uint32_t*)(g_kh + a0 + 8) = h2a; *(uint32_t*)(g_kl + a0 + 8) = l2a;
            *(uint32_t*)(g_kh + a1)     = h1b; *(uint32_t*)(g_kl + a1)     = l1b;
            *(uint32_t*)(g_kh + a1 + 8) = h2b; *(uint32_t*)(g_kl + a1 + 8) = l2b;
        }
    }
}

// ======================= kvb GEMM with fused scatter =======================
__global__ __launch_bounds__(256, 2) void kvb_gemm()
{
    extern __shared__ __align__(16) char smem[];
    const int tid = threadIdx.x, wid = tid >> 5, lane = tid & 31;
    const int warp_m = wid >> 2, warp_n = wid & 3;
    const int m0 = blockIdx.y * 128, n0 = blockIdx.x * 128;
    uint32_t smem_base = smem_u32(smem);

    const char* base[3] = { (const char*)(g_lth + (size_t)m0 * RR),
                            (const char*)(g_Wbh + (size_t)n0 * RR),
                            (const char*)(g_Wbl + (size_t)n0 * RR) };
    const size_t ldbytes = (size_t)RR * 2;
    const int nch = RR >> 5;

    const int lm = lane & 15, lh = lane >> 4;
    const int g = lane >> 3, r = lane & 7;
    const int r4 = lane >> 2, c2 = (lane & 3) * 2;

    float acc[4][4][4];
    #pragma unroll
    for (int i = 0; i < 4; i++)
        #pragma unroll
        for (int j = 0; j < 4; j++)
            #pragma unroll
            for (int e = 0; e < 4; e++) acc[i][j][e] = 0.f;

    GEMM_LOAD_CHUNK(0, 0);
    GEMM_LOAD_CHUNK(1, 1);

    for (int ch = 0; ch < nch; ch++) {
        asm volatile("cp.async.wait_group 1;");
        __syncthreads();
        if (ch + 2 < nch) { GEMM_LOAD_CHUNK(ch + 2, (ch + 2) % NSTAGE); }
        else asm volatile("cp.async.commit_group;");
        const uint32_t smA  = smem_base + (ch % NSTAGE) * GBUF_B;
        const uint32_t smBh = smA + GTILE_B;
        const uint32_t smBl = smBh + GTILE_B;
        #pragma unroll
        for (int k16 = 0; k16 < 2; k16++) {
            uint32_t a[4][4];
            #pragma unroll
            for (int fm = 0; fm < 4; fm++)
                ldsm4(a[fm], smA + ((warp_m * 64 + fm * 16 + lm) * GPAD
                                    + k16 * 16 + lh * 8) * 2);
            uint32_t bh[4][2], bl[4][2];
            #pragma unroll
            for (int fp = 0; fp < 2; fp++) {
                int row = warp_n * 32 + fp * 16 + ((g >> 1) << 3) + r;
                int off = (row * GPAD + (g & 1) * 8 + k16 * 16) * 2;
                uint32_t t4[4];
                ldsm4(t4, smBh + off);
                bh[fp*2][0]=t4[0]; bh[fp*2][1]=t4[1]; bh[fp*2+1][0]=t4[2]; bh[fp*2+1][1]=t4[3];
                ldsm4(t4, smBl + off);
                bl[fp*2][0]=t4[0]; bl[fp*2][1]=t4[1]; bl[fp*2+1][0]=t4[2]; bl[fp*2+1][1]=t4[3];
            }
            #pragma unroll
            for (int fm = 0; fm < 4; fm++)
                #pragma unroll
                for (int fn = 0; fn < 4; fn++) {
                    mma16816(acc[fm][fn], a[fm], bh[fn]);
                    mma16816(acc[fm][fn], a[fm], bl[fn]);
                }
        }
    }

    #pragma unroll
    for (int fm = 0; fm < 4; fm++) {
        int bt0 = m0 + warp_m * 64 + fm * 16 + r4;
        int bt1 = bt0 + 8;
        int t0 = bt0 & (TT - 1), t1 = bt1 & (TT - 1);
        int b  = bt0 >> 11;
        #pragma unroll
        for (int fn = 0; fn < 4; fn++) {
            int n = n0 + warp_n * 32 + fn * 8 + c2;
            int h = n / 112, rr2 = n % 112;
            size_t hb = (size_t)(b * NH + h) * TT;
            if (rr2 < NOPE) {
                size_t a0 = (hb + t0) * HD + rr2, a1 = (hb + t1) * HD + rr2;
                *(uint32_t*)(g_kh + a0) = packh(acc[fm][fn][0], acc[fm][fn][1]);
                *(uint32_t*)(g_kl + a0) = pack_lo_resid(acc[fm][fn][0], acc[fm][fn][1]);
                *(uint32_t*)(g_kh + a1) = packh(acc[fm][fn][2], acc[fm][fn][3]);
                *(uint32_t*)(g_kl + a1) = pack_lo_resid(acc[fm][fn][2], acc[fm][fn][3]);
            } else {
                int d = rr2 - NOPE;
                size_t a0 = (hb + t0) * VD + d, a1 = (hb + t1) * VD + d;
                *(uint32_t*)(g_vh + a0) = packh(acc[fm][fn][0], acc[fm][fn][1]);
                *(uint32_t*)(g_vh + a1) = packh(acc[fm][fn][2], acc[fm][fn][3]);
            }
        }
    }
}

// ======================= Wo GEMM =======================
__global__ __launch_bounds__(256, 2) void wo_gemm(float* __restrict__ C)
{
    extern __shared__ __align__(16) char smem[];
    const int tid = threadIdx.x, wid = tid >> 5, lane = tid & 31;
    const int warp_m = wid >> 2, warp_n = wid & 3;
    const int m0 = blockIdx.y * 128, n0 = blockIdx.x * 128;
    uint32_t smem_base = smem_u32(smem);

    const char* base[3] = { (const char*)(g_aoh + (size_t)m0 * DD),
                            (const char*)(g_Woh + (size_t)n0 * DD),
                            (const char*)(g_Wol + (size_t)n0 * DD) };
    const size_t ldbytes = (size_t)DD * 2;
    const int nch = DD >> 5;

    const int lm = lane & 15, lh = lane >> 4;
    const int g = lane >> 3, r = lane & 7;

    float acc[4][4][4];
    #pragma unroll
    for (int i = 0; i < 4; i++)
        #pragma unroll
        for (int j = 0; j < 4; j++)
            #pragma unroll
            for (int e = 0; e < 4; e++) acc[i][j][e] = 0.f;

    GEMM_LOAD_CHUNK(0, 0);
    GEMM_LOAD_CHUNK(1, 1);

    for (int ch = 0; ch < nch; ch++) {
        asm volatile("cp.async.wait_group 1;");
        __syncthreads();
        if (ch + 2 < nch) { GEMM_LOAD_CHUNK(ch + 2, (ch + 2) % NSTAGE); }
        else asm volatile("cp.async.commit_group;");
        const uint32_t smA  = smem_base + (ch % NSTAGE) * GBUF_B;
        const uint32_t smBh = smA + GTILE_B;
        const uint32_t smBl = smBh + GTILE_B;
        #pragma unroll
        for (int k16 = 0; k16 < 2; k16++) {
            uint32_t a[4][4];
            #pragma unroll
            for (int fm = 0; fm < 4; fm++)
                ldsm4(a[fm], smA + ((warp_m * 64 + fm * 16 + lm) * GPAD
                                    + k16 * 16 + lh * 8) * 2);
            uint32_t bh[4][2], bl[4][2];
            #pragma unroll
            for (int fp = 0; fp < 2; fp++) {
                int row = warp_n * 32 + fp * 16 + ((g >> 1) << 3) + r;
                int off = (row * GPAD + (g & 1) * 8 + k16 * 16) * 2;
                uint32_t t4[4];
                ldsm4(t4, smBh + off);
                bh[fp*2][0]=t4[0]; bh[fp*2][1]=t4[1]; bh[fp*2+1][0]=t4[2]; bh[fp*2+1][1]=t4[3];
                ldsm4(t4, smBl + off);
                bl[fp*2][0]=t4[0]; bl[fp*2][1]=t4[1]; bl[fp*2+1][0]=t4[2]; bl[fp*2+1][1]=t4[3];
            }
            #pragma unroll
            for (int fm = 0; fm < 4; fm++)
                #pragma unroll
                for (int fn = 0; fn < 4; fn++) {
                    mma16816(acc[fm][fn], a[fm], bh[fn]);
                    mma16816(acc[fm][fn], a[fm], bl[fn]);
                }
        }
    }

    const int r4 = lane >> 2, c2 = (lane & 3) * 2;
    #pragma unroll
    for (int fm = 0; fm < 4; fm++) {
        #pragma unroll
        for (int fn = 0; fn < 4; fn++) {
            int m = m0 + warp_m * 64 + fm * 16 + r4;
            int n = n0 + warp_n * 32 + fn * 8 + c2;
            *(float2*)&C[(size_t)m * DD + n] = make_float2(acc[fm][fn][0], acc[fm][fn][1]);
            *(float2*)&C[(size_t)(m + 8) * DD + n] = make_float2(acc[fm][fn][2], acc[fm][fn][3]);
        }
    }
}

// ---------------- flash attention: 2 CTAs/SM, Q-lo in smem ----------------
#define FPAD 72
#define FQLO (3 * 64 * FPAD)    // half offset of persistent Q-lo region

__global__ __launch_bounds__(256, 2) void flash_mma()
{
    __shared__ __align__(16) __half sm[FQLO + 128 * FPAD];   // 46080 B

    const int tid = threadIdx.x, wid = tid >> 5, lane = tid & 31;
    const int bh = blockIdx.y;
    const int b = bh >> 4, h = bh & (NH - 1);
    const int qtile = gridDim.x - 1 - blockIdx.x;
    const int qb = qtile * 128;
    const uint32_t sb = smem_u32(sm);

    const int lm = lane & 15, lh = lane >> 4;
    const int g = lane >> 3, r8 = lane & 7;
    const int r4 = lane >> 2, c2 = (lane & 3) * 2;

    {
        const __half* qhp = g_qh + ((size_t)bh * TT + qb) * HD;
        const __half* qlp = g_ql + ((size_t)bh * TT + qb) * HD;
        for (int i = tid; i < 128 * 8; i += 256) {
            int r = i >> 3, s = i & 7;
            *(uint4*)(sm + r * FPAD + s * 8) = *(const uint4*)(qhp + r * 64 + s * 8);
            *(uint4*)(sm + FQLO + r * FPAD + s * 8) = *(const uint4*)(qlp + r * 64 + s * 8);
        }
    }
    __syncthreads();

    uint32_t qh[4][4];
    #pragma unroll
    for (int ks = 0; ks < 4; ks++)
        ldsm4(qh[ks], sb + ((wid * 16 + lm) * FPAD + ks * 16 + lh * 8) * 2);

    float o[8][4];
    #pragma unroll
    for (int i = 0; i < 8; i++)
        #pragma unroll
        for (int e = 0; e < 4; e++) o[i][e] = 0.f;
    float mrow[2] = { -1e30f, -1e30f };
    float lsum[2] = { 0.f, 0.f };

    const __half* khb = g_kh + (size_t)bh * TT * HD;
    const __half* klb = g_kl + (size_t)bh * TT * HD;
    const __half* vhb = g_vh + (size_t)bh * TT * VD;

    const int ntiles = qtile * 2 + 2;
    const int q0 = qb + wid * 16 + r4;
    const int q1 = q0 + 8;

    const uint32_t oKl = 64 * FPAD * 2;
    const uint32_t oVh = 2 * 64 * FPAD * 2;
    const uint32_t qlo_addr = sb + (FQLO + (wid * 16 + lm) * FPAD + lh * 8) * 2;

    for (int it = 0; it < ntiles; it++) {
        const int j0 = it * 64;
        __syncthreads();
        for (int i = tid; i < 64 * 8; i += 256) {
            int r = i >> 3, s = i & 7;
            size_t gsrc = (size_t)(j0 + r) * 64 + s * 8;
            int dsh = r * FPAD + s * 8;
            *(uint4*)(sm + dsh) = *(const uint4*)(khb + gsrc);
            *(uint4*)(sm + 64 * FPAD + dsh) = *(const uint4*)(klb + gsrc);
            *(uint4*)(sm + 2 * 64 * FPAD + dsh) = *(const uint4*)(vhb + gsrc);
        }
        __syncthreads();

        float s[8][4];
        #pragma unroll
        for (int i = 0; i < 8; i++)
            #pragma unroll
            for (int e = 0; e < 4; e++) s[i][e] = 0.f;

        #pragma unroll
        for (int ks = 0; ks < 4; ks++) {
            uint32_t qlf[4];
            ldsm4(qlf, qlo_addr + ks * 32);
            #pragma unroll
            for (int fp = 0; fp < 4; fp++) {
                const int krow = fp * 16 + ((g >> 1) << 3) + r8;
                uint32_t addr = sb + (krow * FPAD + (g & 1) * 8 + ks * 16) * 2;
                uint32_t bhf[4], blf[4];
                ldsm4(bhf, addr);
                ldsm4(blf, addr + oKl);
                mma16816(s[fp*2],   qh[ks], bhf);
                mma16816(s[fp*2],   qh[ks], blf);
                mma16816(s[fp*2],   qlf,    bhf);
                mma16816(s[fp*2+1], qh[ks], bhf + 2);
                mma16816(s[fp*2+1], qh[ks], blf + 2);
                mma16816(s[fp*2+1], qlf,    bhf + 2);
            }
        }

        const bool need_mask = (it >= ntiles - 2);
        if (need_mask) {
            #pragma unroll
            for (int fn = 0; fn < 8; fn++) {
                #pragma unroll
                for (int e = 0; e < 4; e++) {
                    int kv = j0 + fn * 8 + c2 + (e & 1);
                    int qq = (e < 2) ? q0 : q1;
                    if (kv > qq) s[fn][e] = -1e30f;
                }
            }
        }

        float tm0 = -1e30f, tm1 = -1e30f;
        #pragma unroll
        for (int fn = 0; fn < 8; fn++) {
            tm0 = fmaxf(tm0, fmaxf(s[fn][0], s[fn][1]));
            tm1 = fmaxf(tm1, fmaxf(s[fn][2], s[fn][3]));
        }
        tm0 = fmaxf(tm0, __shfl_xor_sync(~0u, tm0, 1));
        tm0 = fmaxf(tm0, __shfl_xor_sync(~0u, tm0, 2));
        tm1 = fmaxf(tm1, __shfl_xor_sync(~0u, tm1, 1));
        tm1 = fmaxf(tm1, __shfl_xor_sync(~0u, tm1, 2));

        float mn0 = fmaxf(mrow[0], tm0), mn1 = fmaxf(mrow[1], tm1);
        float cr0 = __expf(mrow[0] - mn0), cr1 = __expf(mrow[1] - mn1);
        mrow[0] = mn0; mrow[1] = mn1;
        lsum[0] *= cr0; lsum[1] *= cr1;
        #pragma unroll
        for (int fn = 0; fn < 8; fn++) {
            o[fn][0] *= cr0; o[fn][1] *= cr0;
            o[fn][2] *= cr1; o[fn][3] *= cr1;
        }

        #pragma unroll
        for (int fn = 0; fn < 8; fn++) {
            s[fn][0] = __expf(s[fn][0] - mn0);
            s[fn][1] = __expf(s[fn][1] - mn0);
            s[fn][2] = __expf(s[fn][2] - mn1);
            s[fn][3] = __expf(s[fn][3] - mn1);
            lsum[0] += s[fn][0] + s[fn][1];
            lsum[1] += s[fn][2] + s[fn][3];
        }

        #pragma unroll
        for (int ks = 0; ks < 4; ks++) {
            uint32_t aph[4], apl[4];
            aph[0] = packh(s[ks*2][0], s[ks*2][1]);
            aph[1] = packh(s[ks*2][2], s[ks*2][3]);
            aph[2] = packh(s[ks*2+1][0], s[ks*2+1][1]);
            aph[3] = packh(s[ks*2+1][2], s[ks*2+1][3]);
            apl[0] = pack_lo_resid(s[ks*2][0], s[ks*2][1]);
            apl[1] = pack_lo_resid(s[ks*2][2], s[ks*2][3]);
            apl[2] = pack_lo_resid(s[ks*2+1][0], s[ks*2+1][1]);
            apl[3] = pack_lo_resid(s[ks*2+1][2], s[ks*2+1][3]);

            const int vrow = ks * 16 + (g & 1) * 8 + r8;
            #pragma unroll
            for (int np = 0; np < 4; np++) {
                const int vcol = np * 16 + lh * 8;
                uint32_t addr = sb + oVh + (vrow * FPAD + vcol) * 2;
                uint32_t bvh[4];
                ldsm4t(bvh, addr);
                mma16816(o[np*2],   aph, bvh);
                mma16816(o[np*2],   apl, bvh);
                mma16816(o[np*2+1], aph, bvh + 2);
                mma16816(o[np*2+1], apl, bvh + 2);
            }
        }
    }

    lsum[0] += __shfl_xor_sync(~0u, lsum[0], 1);
    lsum[0] += __shfl_xor_sync(~0u, lsum[0], 2);
    lsum[1] += __shfl_xor_sync(~0u, lsum[1], 1);
    lsum[1] += __shfl_xor_sync(~0u, lsum[1], 2);
    const float inv0 = 1.f / lsum[0], inv1 = 1.f / lsum[1];

    __half* ob0 = g_aoh + ((size_t)(b * TT + q0)) * (NH * VD) + h * VD;
    __half* ob1 = g_aoh + ((size_t)(b * TT + q1)) * (NH * VD) + h * VD;
    #pragma unroll
    for (int fn = 0; fn < 8; fn++) {
        *(uint32_t*)(ob0 + fn * 8 + c2) = packh(o[fn][0] * inv0, o[fn][1] * inv0);
        *(uint32_t*)(ob1 + fn * 8 + c2) = packh(o[fn][2] * inv1, o[fn][3] * inv1);
    }
}

// ---------------- launch ----------------
extern "C" void kernel_launch(void* const* d_in, const int* in_sizes, int n_in,
                              void* d_out, int out_size)
{
    const float* x    = (const float*)d_in[0];
    const float* cosp = (const float*)d_in[1];
    const float* sinp = (const float*)d_in[2];
    const float* Wq   = (const float*)d_in[3];
    const float* qw   = (const float*)d_in[4];
    const float* Wkva = (const float*)d_in[5];
    const float* kvaw = (const float*)d_in[6];
    const float* Wkvb = (const float*)d_in[7];
    const float* Wo   = (const float*)d_in[8];
    float* out = (float*)d_out;

    cudaFuncSetAttribute(proj1_gemm, cudaFuncAttributeMaxDynamicSharedMemorySize, NSTAGE * GBUF_B);
    cudaFuncSetAttribute(kvb_gemm,   cudaFuncAttributeMaxDynamicSharedMemorySize, NSTAGE * GBUF_B);
    cudaFuncSetAttribute(wo_gemm,    cudaFuncAttributeMaxDynamicSharedMemorySize, NSTAGE * GBUF_B);

    cvt_all<<<(QTOT + 255) / 256, 256>>>(x, Wq, Wkva, Wkvb, Wo);

    {
        dim3 g(W1_ROWS / 128, MTOT / 128);
        proj1_gemm<<<g, 256, NSTAGE * GBUF_B>>>(cosp, sinp, qw, kvaw);
    }
    {
        dim3 g(KVB_N / 128, MTOT / 128);
        kvb_gemm<<<g, 256, NSTAGE * GBUF_B>>>();
    }
    {
        dim3 g(TT / 128, BB * NH);
        flash_mma<<<g, 256>>>();
    }
    {
        dim3 g(DD / 128, MTOT / 128);
        wo_gemm<<<g, 256, NSTAGE * GBUF_B>>>(out);   // <-- fixed: dynamic smem restored
    }
}